// round 12
// baseline (speedup 1.0000x reference)
#include <cuda_runtime.h>
#include <math.h>
#include <stdint.h>

#define B_  4
#define T_  2048
#define D_  128
#define H_  8
#define BH_ (B_*H_)
#define NEGINF (-1e30f)

// scratch (device globals -- no allocation allowed)
// g_q/g_k: [bh][t][perm-d]  perm(d) = (d%4)*32 + d/4
// g_v:     [bh][key-block 0..31][d 0..127][perm-key]  perm(kt) = (kt%4)*16 + kt/4
__device__ float g_q [BH_*T_*D_];
__device__ float g_k [BH_*T_*D_];
__device__ float g_v [BH_*T_*D_];
__device__ float g_ao[B_*T_*H_*D_];
// pre-rounded tf32 operands
__device__ float g_x [B_*T_*D_];
__device__ float g_wq[D_*H_*D_];
__device__ float g_wk[D_*H_*D_];
__device__ float g_wv[D_*H_*D_];
__device__ float g_wu[H_*D_*D_];

__device__ __forceinline__ unsigned f2tf(float f){
    unsigned u; asm("cvt.rna.tf32.f32 %0, %1;" : "=r"(u) : "f"(f)); return u;
}
__device__ __forceinline__ float f2tff(float f){
    return __uint_as_float(f2tf(f));
}
__device__ __forceinline__ uint4 f2tf4(float4 v){
    return make_uint4(f2tf(v.x), f2tf(v.y), f2tf(v.z), f2tf(v.w));
}
__device__ __forceinline__ uint4 f4bits(float4 v){
    return make_uint4(__float_as_uint(v.x), __float_as_uint(v.y),
                      __float_as_uint(v.z), __float_as_uint(v.w));
}
__device__ __forceinline__ uint32_t saddr(const void* p){
    return (uint32_t)__cvta_generic_to_shared(p);
}
__device__ __forceinline__ void cpa16(uint32_t dst, const void* src){
    asm volatile("cp.async.cg.shared.global [%0], [%1], 16;" :: "r"(dst), "l"(src));
}
#define CP_COMMIT  asm volatile("cp.async.commit_group;")
#define CP_WAIT0   asm volatile("cp.async.wait_group 0;")
#define CP_WAIT1   asm volatile("cp.async.wait_group 1;")

__device__ __forceinline__ void mma8(float4& d,
    unsigned a0, unsigned a1, unsigned a2, unsigned a3,
    unsigned b0, unsigned b1)
{
    asm volatile(
        "mma.sync.aligned.m16n8k8.row.col.f32.tf32.tf32.f32 "
        "{%0,%1,%2,%3},{%4,%5,%6,%7},{%8,%9},{%0,%1,%2,%3};"
        : "+f"(d.x), "+f"(d.y), "+f"(d.z), "+f"(d.w)
        : "r"(a0), "r"(a1), "r"(a2), "r"(a3), "r"(b0), "r"(b1));
}

// ---------------------------------------------------------------------------
// Kernel 0: pre-round inputs to tf32 (Wv gets 128^-0.25 baked in).
// ---------------------------------------------------------------------------
__global__ __launch_bounds__(256, 4)
void prep_kernel(const float* __restrict__ x,  const float* __restrict__ wq,
                 const float* __restrict__ wk, const float* __restrict__ wv,
                 const float* __restrict__ wu)
{
    const int seg = blockIdx.y;
    const float* src; float* dst; int n4; float s = 1.0f;
    if      (seg == 0) { src = x;  dst = g_x;  n4 = (B_*T_*D_)/4; }
    else if (seg == 1) { src = wq; dst = g_wq; n4 = (D_*H_*D_)/4; }
    else if (seg == 2) { src = wk; dst = g_wk; n4 = (D_*H_*D_)/4; }
    else if (seg == 3) { src = wv; dst = g_wv; n4 = (D_*H_*D_)/4; s = 0.29730177875068026f; }
    else               { src = wu; dst = g_wu; n4 = (H_*D_*D_)/4; }

    for (int i = blockIdx.x * blockDim.x + threadIdx.x; i < n4;
         i += gridDim.x * blockDim.x) {
        float4 v = ((const float4*)src)[i];
        v.x *= s; v.y *= s; v.z *= s; v.w *= s;
        ((uint4*)dst)[i] = f2tf4(v);
    }
}

// ---------------------------------------------------------------------------
// Kernel 1: fused QKV projection, tf32 MMA, cp.async, 2 CTAs/SM.
// Block tile 128x64, warp tile 32x32 (4x2 warps).
// Epilogue writes q/k permuted over d, v transposed + key-permuted (see top).
// ---------------------------------------------------------------------------
__global__ __launch_bounds__(256, 2)
void qkv_kernel()
{
    extern __shared__ unsigned smu[];
    unsigned* Xs = smu;             // [128][132]
    unsigned* Ws = smu + 128*132;   // [128][72]

    const int bx = blockIdx.x;     // 64-col tile (0..15)
    const int by = blockIdx.y;     // 128-row tile
    const int mat = blockIdx.z;
    const float* Wg = (mat == 0) ? g_wq : (mat == 1 ? g_wk : g_wv);
    float* outp     = (mat == 0) ? g_q  : (mat == 1 ? g_k  : g_v);

    const int tid = threadIdx.x;
    const int wid = tid >> 5, lane = tid & 31;
    const int g = lane >> 2, c = lane & 3;
    const int wm2 = wid >> 1, wn2 = wid & 1;

    // async loads: X [128x128], W [128x64]
    #pragma unroll
    for (int it = 0; it < 16; ++it) {
        int lin = it * 256 + tid;
        int m = lin >> 5, c4 = lin & 31;
        cpa16(saddr(Xs + m*132 + c4*4), g_x + (size_t)(by*128 + m)*128 + c4*4);
    }
    #pragma unroll
    for (int it = 0; it < 8; ++it) {
        int lin = it * 256 + tid;
        int k = lin >> 4, n4 = lin & 15;
        cpa16(saddr(Ws + k*72 + n4*4), Wg + (size_t)k*1024 + bx*64 + n4*4);
    }
    CP_COMMIT;
    CP_WAIT0;
    __syncthreads();

    float4 acc[2][4];
    #pragma unroll
    for (int i = 0; i < 2; ++i)
        #pragma unroll
        for (int j = 0; j < 4; ++j) acc[i][j] = make_float4(0.f, 0.f, 0.f, 0.f);

    #pragma unroll
    for (int k8 = 0; k8 < 16; ++k8) {
        int kk = k8 * 8;
        unsigned a[2][4];
        #pragma unroll
        for (int mt = 0; mt < 2; ++mt) {
            int r = wm2*32 + mt*16 + g;
            a[mt][0] = Xs[r*132 + kk + c];
            a[mt][1] = Xs[(r+8)*132 + kk + c];
            a[mt][2] = Xs[r*132 + kk + c + 4];
            a[mt][3] = Xs[(r+8)*132 + kk + c + 4];
        }
        #pragma unroll
        for (int nt = 0; nt < 4; ++nt) {
            unsigned b0 = Ws[(kk+c  )*72 + wn2*32 + nt*8 + g];
            unsigned b1 = Ws[(kk+c+4)*72 + wn2*32 + nt*8 + g];
            mma8(acc[0][nt], a[0][0], a[0][1], a[0][2], a[0][3], b0, b1);
            mma8(acc[1][nt], a[1][0], a[1][1], a[1][2], a[1][3], b0, b1);
        }
    }

    // epilogue: tf32-rounded, permuted layouts for attn's cp.async
    const int hh = bx >> 1;
    #pragma unroll
    for (int mt = 0; mt < 2; ++mt) {
        int mg0 = by*128 + wm2*32 + mt*16 + g;
        int bbi = mg0 >> 11;                   // batch (row+8 never crosses)
        int t0  = mg0 & (T_ - 1);
        int t1  = t0 + 8;
        #pragma unroll
        for (int nt = 0; nt < 4; ++nt) {
            int d0 = (bx & 1)*64 + wn2*32 + nt*8 + 2*c;
            float vx = f2tff(acc[mt][nt].x), vy = f2tff(acc[mt][nt].y);
            float vz = f2tff(acc[mt][nt].z), vw = f2tff(acc[mt][nt].w);
            if (mat < 2) {
                int pd0 = ((d0 & 3) << 5) + (d0 >> 2);
                int pd1 = (((d0+1) & 3) << 5) + (d0 >> 2);
                size_t base0 = ((size_t)(bbi*H_ + hh)*T_ + t0)*D_;
                size_t base1 = ((size_t)(bbi*H_ + hh)*T_ + t1)*D_;
                outp[base0 + pd0] = vx;  outp[base0 + pd1] = vy;
                outp[base1 + pd0] = vz;  outp[base1 + pd1] = vw;
            } else {
                int nb = t0 >> 6, kt0 = t0 & 63;
                int s0 = ((kt0 & 3) << 4) + (kt0 >> 2);
                int s1 = s0 + 2;                     // t0+8: same block, j+2
                size_t rb = ((size_t)(bbi*H_ + hh)*32 + nb)*128;
                outp[(rb + d0    )*64 + s0] = vx;
                outp[(rb + d0 + 1)*64 + s0] = vy;
                outp[(rb + d0    )*64 + s1] = vz;
                outp[(rb + d0 + 1)*64 + s1] = vw;
            }
        }
    }
}

// ---------------------------------------------------------------------------
// Kernel 2: causal flash attention, tf32 MMA, cp.async pipelined K/V,
// k-permuted smem layouts -> all fragment loads are LDS.128.
// Qs/Ks: [row][4 sections x 36 words]   (k-dim permuted, stride 144)
// Vst:   [d][4 sections x 20 words]     (key-dim permuted, stride 80)
// Ps:    [qrow][4 sections x 20 words]  (key-dim permuted, stride 80)
// ---------------------------------------------------------------------------
__global__ __launch_bounds__(256, 1)
void attn_kernel()
{
    extern __shared__ unsigned smu[];
    unsigned* Qs  = smu;                    // [128][144]
    unsigned* Ks  = Qs + 128*144;           // [ 64][144]
    unsigned* Vst = Ks +  64*144;           // [128][ 80]
    unsigned* Ps  = Vst + 128*80;           // [128][ 80]
    float*   red  = (float*)(Ps + 128*80);  // [128]

    const int bh    = blockIdx.y;
    const int qi    = (int)gridDim.x - 1 - (int)blockIdx.x;  // big tiles first
    const int qbase = qi * 128;
    const int tid   = threadIdx.x;
    const int wid   = tid >> 5, lane = tid & 31;
    const int g = lane >> 2, c = lane & 3;
    const int wbase = wid * 16;              // S-layout row base
    const int wm2 = wid >> 1, wn2 = wid & 1; // PV layout

    const float* qg = g_q + ((size_t)bh * T_ + qbase) * D_;
    const float* kg = g_k + (size_t)bh * T_ * D_;
    const float* vg = g_v + (size_t)bh * 32 * 128 * 64;  // [block][d][64]

    // prologue: Q, K0, V0 via cp.async (3 groups)
    #pragma unroll
    for (int it = 0; it < 16; ++it) {
        int lin = it * 256 + tid;
        int m = lin >> 5, ch = lin & 31;             // ch: 32 16B-chunks/row
        cpa16(saddr(Qs + m*144 + (ch>>3)*36 + (ch&7)*4), qg + m*128 + ch*4);
    }
    CP_COMMIT;
    #pragma unroll
    for (int it = 0; it < 8; ++it) {
        int lin = it * 256 + tid;
        int m = lin >> 5, ch = lin & 31;
        cpa16(saddr(Ks + m*144 + (ch>>3)*36 + (ch&7)*4), kg + m*128 + ch*4);
    }
    CP_COMMIT;
    #pragma unroll
    for (int it = 0; it < 8; ++it) {
        int lin = it * 256 + tid;
        int d = lin >> 4, ch = lin & 15;             // ch: 16 16B-chunks/row
        cpa16(saddr(Vst + d*80 + (ch>>2)*20 + (ch&3)*4), vg + d*64 + ch*4);
    }
    CP_COMMIT;
    CP_WAIT0;
    __syncthreads();

    float m0 = NEGINF, m1 = NEGINF, l0 = 0.f, l1 = 0.f;
    float4 oacc[2][8];
    #pragma unroll
    for (int i = 0; i < 2; ++i)
        #pragma unroll
        for (int j = 0; j < 8; ++j) oacc[i][j] = make_float4(0.f, 0.f, 0.f, 0.f);

    const int   ntiles = 2 * qi + 2;
    const float sscale = 0.088388347648318447f;   // 128^-0.5

    // per-thread fragment base offsets
    const unsigned* qA0 = Qs + (wbase+g  )*144 + c*36;
    const unsigned* qA1 = Qs + (wbase+g+8)*144 + c*36;

    for (int n = 0; n < ntiles; ++n) {
        const bool pre = (n + 1 < ntiles);

        // S = Q K^T : warp rows [wbase, wbase+16), all 64 cols
        float4 sacc[8];
        #pragma unroll
        for (int nt = 0; nt < 8; ++nt) sacc[nt] = make_float4(0.f, 0.f, 0.f, 0.f);

        #pragma unroll
        for (int kp = 0; kp < 8; ++kp) {        // 2 k8-steps per kp
            uint4 aL = *(const uint4*)(qA0 + 4*kp);
            uint4 aH = *(const uint4*)(qA1 + 4*kp);
            #pragma unroll
            for (int nt = 0; nt < 8; ++nt) {
                uint4 bb = *(const uint4*)(Ks + (nt*8+g)*144 + c*36 + 4*kp);
                mma8(sacc[nt], aL.x, aH.x, aL.y, aH.y, bb.x, bb.y);
                mma8(sacc[nt], aL.z, aH.z, aL.w, aH.w, bb.z, bb.w);
            }
        }
        __syncthreads();   // bar1: all warps done reading Ks

        // async-stage K_{n+1} (arrives during softmax+PV)
        if (pre) {
            const float* kt = kg + (size_t)(n+1) * 64 * D_;
            #pragma unroll
            for (int it = 0; it < 8; ++it) {
                int lin = it * 256 + tid;
                int m = lin >> 5, ch = lin & 31;
                cpa16(saddr(Ks + m*144 + (ch>>3)*36 + (ch&7)*4), kt + m*128 + ch*4);
            }
            CP_COMMIT;
        }

        // scale
        #pragma unroll
        for (int nt = 0; nt < 8; ++nt) {
            sacc[nt].x *= sscale; sacc[nt].y *= sscale;
            sacc[nt].z *= sscale; sacc[nt].w *= sscale;
        }
        // causal mask (only last two tiles can touch the diagonal)
        if (n >= 2 * qi) {
            int rg0 = qbase + wbase + g, rg1 = rg0 + 8;
            #pragma unroll
            for (int nt = 0; nt < 8; ++nt) {
                int c0 = n*64 + nt*8 + 2*c;
                if (c0     > rg0) sacc[nt].x = NEGINF;
                if (c0 + 1 > rg0) sacc[nt].y = NEGINF;
                if (c0     > rg1) sacc[nt].z = NEGINF;
                if (c0 + 1 > rg1) sacc[nt].w = NEGINF;
            }
        }

        // online softmax: rows r0 = wbase+g, r1 = r0+8 (4-lane group reduce)
        float mx0 = NEGINF, mx1 = NEGINF;
        #pragma unroll
        for (int nt = 0; nt < 8; ++nt) {
            mx0 = fmaxf(mx0, fmaxf(sacc[nt].x, sacc[nt].y));
            mx1 = fmaxf(mx1, fmaxf(sacc[nt].z, sacc[nt].w));
        }
        mx0 = fmaxf(mx0, __shfl_xor_sync(0xffffffffu, mx0, 1));
        mx0 = fmaxf(mx0, __shfl_xor_sync(0xffffffffu, mx0, 2));
        mx1 = fmaxf(mx1, __shfl_xor_sync(0xffffffffu, mx1, 1));
        mx1 = fmaxf(mx1, __shfl_xor_sync(0xffffffffu, mx1, 2));

        float mn0 = fmaxf(m0, mx0), mn1 = fmaxf(m1, mx1);
        float al0 = __expf(m0 - mn0), al1 = __expf(m1 - mn1);
        m0 = mn0; m1 = mn1;

        int r0 = wbase + g, r1 = r0 + 8;
        // Ps write offsets: col = nt*8+2c -> sec = (2c)&3 (x), (2c+1)&3 (y),
        // j = 2nt + (c>>1)
        unsigned* psx0 = Ps + r0*80 + ((2*c  )&3)*20 + (c>>1);
        unsigned* psy0 = Ps + r0*80 + ((2*c+1)&3)*20 + (c>>1);
        unsigned* psx1 = Ps + r1*80 + ((2*c  )&3)*20 + (c>>1);
        unsigned* psy1 = Ps + r1*80 + ((2*c+1)&3)*20 + (c>>1);
        float rs0 = 0.f, rs1 = 0.f;
        #pragma unroll
        for (int nt = 0; nt < 8; ++nt) {
            float px = __expf(sacc[nt].x - mn0);
            float py = __expf(sacc[nt].y - mn0);
            float pz = __expf(sacc[nt].z - mn1);
            float pw = __expf(sacc[nt].w - mn1);
            rs0 += px + py; rs1 += pz + pw;
            psx0[2*nt] = f2tf(px);  psy0[2*nt] = f2tf(py);
            psx1[2*nt] = f2tf(pz);  psy1[2*nt] = f2tf(pw);
        }
        rs0 += __shfl_xor_sync(0xffffffffu, rs0, 1);
        rs0 += __shfl_xor_sync(0xffffffffu, rs0, 2);
        rs1 += __shfl_xor_sync(0xffffffffu, rs1, 1);
        rs1 += __shfl_xor_sync(0xffffffffu, rs1, 2);
        l0 = l0 * al0 + rs0;
        l1 = l1 * al1 + rs1;
        if (c == 0) { red[r0] = al0; red[r1] = al1; }

        // ensure V_n arrived (oldest pending group); K_{n+1} may still fly
        if (pre) { CP_WAIT1; } else { CP_WAIT0; }
        __syncthreads();   // bar2: Ps + alpha + V_n visible

        // rescale O (PV layout rows: wm2*32 + mt*16 + {g, g+8})
        float af0 = red[wm2*32      + g], af1 = red[wm2*32      + g + 8];
        float af2 = red[wm2*32 + 16 + g], af3 = red[wm2*32 + 16 + g + 8];
        #pragma unroll
        for (int nt = 0; nt < 8; ++nt) {
            oacc[0][nt].x *= af0; oacc[0][nt].y *= af0;
            oacc[0][nt].z *= af1; oacc[0][nt].w *= af1;
            oacc[1][nt].x *= af2; oacc[1][nt].y *= af2;
            oacc[1][nt].z *= af3; oacc[1][nt].w *= af3;
        }

        // O += P @ V  (warp: 32 rows x 64 cols), vectorized fragments
        #pragma unroll
        for (int kp = 0; kp < 4; ++kp) {     // 2 k8-steps per kp
            uint4 pL0 = *(const uint4*)(Ps + (wm2*32   + g)*80 + c*20 + 4*kp);
            uint4 pH0 = *(const uint4*)(Ps + (wm2*32+ 8+ g)*80 + c*20 + 4*kp);
            uint4 pL1 = *(const uint4*)(Ps + (wm2*32+16+ g)*80 + c*20 + 4*kp);
            uint4 pH1 = *(const uint4*)(Ps + (wm2*32+24+ g)*80 + c*20 + 4*kp);
            #pragma unroll
            for (int nt = 0; nt < 8; ++nt) {
                uint4 bb = *(const uint4*)(Vst + (wn2*64+nt*8+g)*80 + c*20 + 4*kp);
                mma8(oacc[0][nt], pL0.x, pH0.x, pL0.y, pH0.y, bb.x, bb.y);
                mma8(oacc[0][nt], pL0.z, pH0.z, pL0.w, pH0.w, bb.z, bb.w);
                mma8(oacc[1][nt], pL1.x, pH1.x, pL1.y, pH1.y, bb.x, bb.y);
                mma8(oacc[1][nt], pL1.z, pH1.z, pL1.w, pH1.w, bb.z, bb.w);
            }
        }

        // ensure K_{n+1} arrived before next S reads Ks
        CP_WAIT0;
        __syncthreads();   // bar3: K_{n+1} visible; Vst free

        // async-stage V_{n+1} (arrives during next S + softmax)
        if (pre) {
            const float* vt = vg + (size_t)(n+1) * 128 * 64;
            #pragma unroll
            for (int it = 0; it < 8; ++it) {
                int lin = it * 256 + tid;
                int d = lin >> 4, ch = lin & 15;
                cpa16(saddr(Vst + d*80 + (ch>>2)*20 + (ch&3)*4), vt + d*64 + ch*4);
            }
            CP_COMMIT;
        }
    }

    // final normalization: pass l across layouts via smem
    __syncthreads();
    if (c == 0) { red[wbase + g] = l0; red[wbase + g + 8] = l1; }
    __syncthreads();
    float inv0 = 1.f / red[wm2*32      + g], inv1 = 1.f / red[wm2*32      + g + 8];
    float inv2 = 1.f / red[wm2*32 + 16 + g], inv3 = 1.f / red[wm2*32 + 16 + g + 8];

    // outputs tf32-rounded so proj can raw-copy them (g_ao stays linear)
    const int bb = bh >> 3, hh = bh & 7;
    #pragma unroll
    for (int mt = 0; mt < 2; ++mt) {
        float iv0 = (mt == 0) ? inv0 : inv2;
        float iv1 = (mt == 0) ? inv1 : inv3;
        int t0 = qbase + wm2*32 + mt*16 + g;
        #pragma unroll
        for (int nt = 0; nt < 8; ++nt) {
            int d = wn2*64 + nt*8 + 2*c;
            float* p0 = g_ao + ((size_t)(bb*T_ + t0))*(H_*D_) + hh*128 + d;
            *(float2*)p0 = make_float2(f2tff(oacc[mt][nt].x * iv0),
                                       f2tff(oacc[mt][nt].y * iv0));
            float* p1 = g_ao + ((size_t)(bb*T_ + t0 + 8))*(H_*D_) + hh*128 + d;
            *(float2*)p1 = make_float2(f2tff(oacc[mt][nt].z * iv1),
                                       f2tff(oacc[mt][nt].w * iv1));
        }
    }
}

// ---------------------------------------------------------------------------
// Kernel 3: output projection, tf32 MMA, register double-buffered k-chunks.
// ---------------------------------------------------------------------------
__global__ __launch_bounds__(256, 1)
void proj_kernel(const float* __restrict__ bu, float* __restrict__ out)
{
    extern __shared__ unsigned smu[];
    unsigned* As = smu;           // [64][68]
    unsigned* Bs = smu + 64*68;   // [64][136]

    const int by  = blockIdx.x;
    const int tid = threadIdx.x;
    const int wid = tid >> 5, lane = tid & 31;
    const int g = lane >> 2, c = lane & 3;
    const int wm = wid >> 1, wn = wid & 1;

    float4 acc[8];
    #pragma unroll
    for (int j = 0; j < 8; ++j) acc[j] = make_float4(0.f, 0.f, 0.f, 0.f);

    float4 areg[4], breg[8];
    #pragma unroll
    for (int it = 0; it < 4; ++it) {
        int lin = it * 256 + tid;
        int m = lin >> 4, c4 = lin & 15;
        areg[it] = *(const float4*)(g_ao + (size_t)(by*64 + m)*1024 + c4*4);
    }
    #pragma unroll
    for (int it = 0; it < 8; ++it) {
        int lin = it * 256 + tid;
        int k = lin >> 5, n4 = lin & 31;
        breg[it] = *(const float4*)(g_wu + (size_t)k*128 + n4*4);
    }

    for (int kc = 0; kc < 16; ++kc) {
        __syncthreads();
        #pragma unroll
        for (int it = 0; it < 4; ++it) {
            int lin = it * 256 + tid;
            int m = lin >> 4, c4 = lin & 15;
            *(uint4*)(As + m*68 + c4*4) = f4bits(areg[it]);
        }
        #pragma unroll
        for (int it = 0; it < 8; ++it) {
            int lin = it * 256 + tid;
            int k = lin >> 5, n4 = lin & 31;
            *(uint4*)(Bs + k*136 + n4*4) = f4bits(breg[it]);
        }
        __syncthreads();

        if (kc < 15) {
            #pragma unroll
            for (int it = 0; it < 4; ++it) {
                int lin = it * 256 + tid;
                int m = lin >> 4, c4 = lin & 15;
                areg[it] = *(const float4*)(g_ao + (size_t)(by*64 + m)*1024
                                                 + (kc+1)*64 + c4*4);
            }
            #pragma unroll
            for (int it = 0; it < 8; ++it) {
                int lin = it * 256 + tid;
                int k = lin >> 5, n4 = lin & 31;
                breg[it] = *(const float4*)(g_wu + (size_t)((kc+1)*64 + k)*128 + n4*4);
            }
        }

        #pragma unroll
        for (int k8 = 0; k8 < 8; ++k8) {
            int kk = k8 * 8;
            int r = wm*16 + g;
            unsigned a0 = As[r*68 + kk + c];
            unsigned a1 = As[(r+8)*68 + kk + c];
            unsigned a2 = As[r*68 + kk + c + 4];
            unsigned a3 = As[(r+8)*68 + kk + c + 4];
            #pragma unroll
            for (int nt = 0; nt < 8; ++nt) {
                unsigned b0 = Bs[(kk+c  )*136 + wn*64 + nt*8 + g];
                unsigned b1 = Bs[(kk+c+4)*136 + wn*64 + nt*8 + g];
                mma8(acc[nt], a0, a1, a2, a3, b0, b1);
            }
        }
    }

    #pragma unroll
    for (int nt = 0; nt < 8; ++nt) {
        int d = wn*64 + nt*8 + 2*c;
        float bv0 = bu[d], bv1 = bu[d + 1];
        int m0 = by*64 + wm*16 + g;
        *(float2*)(out + (size_t)m0*128 + d) =
            make_float2(acc[nt].x + bv0, acc[nt].y + bv1);
        *(float2*)(out + (size_t)(m0 + 8)*128 + d) =
            make_float2(acc[nt].z + bv0, acc[nt].w + bv1);
    }
}

// ---------------------------------------------------------------------------
extern "C" void kernel_launch(void* const* d_in, const int* in_sizes, int n_in,
                              void* d_out, int out_size)
{
    const float* x  = (const float*)d_in[0];
    const float* Wq = (const float*)d_in[1];
    const float* Wk = (const float*)d_in[2];
    const float* Wv = (const float*)d_in[3];
    const float* Wu = (const float*)d_in[4];
    const float* bu = (const float*)d_in[5];
    float* out = (float*)d_out;

    const int SMEM1 = (128*132 + 128*72) * (int)sizeof(unsigned);                  // 104448
    const int SMEM2 = (128*144 + 64*144 + 128*80 + 128*80 + 128) * (int)sizeof(unsigned); // 193024
    const int SMEM3 = (64*68 + 64*136) * (int)sizeof(unsigned);                    // 52224

    cudaFuncSetAttribute(qkv_kernel,  cudaFuncAttributeMaxDynamicSharedMemorySize, SMEM1);
    cudaFuncSetAttribute(attn_kernel, cudaFuncAttributeMaxDynamicSharedMemorySize, SMEM2);
    cudaFuncSetAttribute(proj_kernel, cudaFuncAttributeMaxDynamicSharedMemorySize, SMEM3);

    prep_kernel<<<dim3(128, 5), 256>>>(x, Wq, Wk, Wv, Wu);
    qkv_kernel<<<dim3(16, 64, 3), 256, SMEM1>>>();
    attn_kernel<<<dim3(16, 32), 256, SMEM2>>>();
    proj_kernel<<<dim3(128), 256, SMEM3>>>(bu, out);
}

// round 14
// speedup vs baseline: 1.6617x; 1.6617x over previous
#include <cuda_runtime.h>
#include <math.h>
#include <stdint.h>

#define B_  4
#define T_  2048
#define D_  128
#define H_  8
#define BH_ (B_*H_)
#define NEGINF (-1e30f)

// scratch (device globals -- no allocation allowed)
// g_q/g_k: [bh][t][perm-d]  perm(d) = (d%4)*32 + d/4
// g_v:     [bh][key-block 0..31][d 0..127][perm-key]  perm(kt) = (kt%4)*16 + kt/4
__device__ float g_q [BH_*T_*D_];
__device__ float g_k [BH_*T_*D_];
__device__ float g_v [BH_*T_*D_];
__device__ float g_ao[B_*T_*H_*D_];
// pre-rounded tf32 operands
__device__ float g_x [B_*T_*D_];
__device__ float g_wq[D_*H_*D_];
__device__ float g_wk[D_*H_*D_];
__device__ float g_wv[D_*H_*D_];
__device__ float g_wu[H_*D_*D_];

__device__ __forceinline__ unsigned f2tf(float f){
    unsigned u; asm("cvt.rna.tf32.f32 %0, %1;" : "=r"(u) : "f"(f)); return u;
}
__device__ __forceinline__ float f2tff(float f){
    return __uint_as_float(f2tf(f));
}
__device__ __forceinline__ uint4 f2tf4(float4 v){
    return make_uint4(f2tf(v.x), f2tf(v.y), f2tf(v.z), f2tf(v.w));
}
__device__ __forceinline__ uint4 f4bits(float4 v){
    return make_uint4(__float_as_uint(v.x), __float_as_uint(v.y),
                      __float_as_uint(v.z), __float_as_uint(v.w));
}
__device__ __forceinline__ uint32_t saddr(const void* p){
    return (uint32_t)__cvta_generic_to_shared(p);
}
__device__ __forceinline__ void cpa16(uint32_t dst, const void* src){
    asm volatile("cp.async.cg.shared.global [%0], [%1], 16;" :: "r"(dst), "l"(src));
}
#define CP_COMMIT  asm volatile("cp.async.commit_group;")
#define CP_WAIT0   asm volatile("cp.async.wait_group 0;")
#define CP_WAIT1   asm volatile("cp.async.wait_group 1;")

__device__ __forceinline__ void mma8(float4& d,
    unsigned a0, unsigned a1, unsigned a2, unsigned a3,
    unsigned b0, unsigned b1)
{
    asm volatile(
        "mma.sync.aligned.m16n8k8.row.col.f32.tf32.tf32.f32 "
        "{%0,%1,%2,%3},{%4,%5,%6,%7},{%8,%9},{%0,%1,%2,%3};"
        : "+f"(d.x), "+f"(d.y), "+f"(d.z), "+f"(d.w)
        : "r"(a0), "r"(a1), "r"(a2), "r"(a3), "r"(b0), "r"(b1));
}

// ---------------------------------------------------------------------------
// Kernel 0: pre-round inputs to tf32 (Wv gets 128^-0.25 baked in).
// ---------------------------------------------------------------------------
__global__ __launch_bounds__(256, 4)
void prep_kernel(const float* __restrict__ x,  const float* __restrict__ wq,
                 const float* __restrict__ wk, const float* __restrict__ wv,
                 const float* __restrict__ wu)
{
    const int seg = blockIdx.y;
    const float* src; float* dst; int n4; float s = 1.0f;
    if      (seg == 0) { src = x;  dst = g_x;  n4 = (B_*T_*D_)/4; }
    else if (seg == 1) { src = wq; dst = g_wq; n4 = (D_*H_*D_)/4; }
    else if (seg == 2) { src = wk; dst = g_wk; n4 = (D_*H_*D_)/4; }
    else if (seg == 3) { src = wv; dst = g_wv; n4 = (D_*H_*D_)/4; s = 0.29730177875068026f; }
    else               { src = wu; dst = g_wu; n4 = (H_*D_*D_)/4; }

    for (int i = blockIdx.x * blockDim.x + threadIdx.x; i < n4;
         i += gridDim.x * blockDim.x) {
        float4 v = ((const float4*)src)[i];
        v.x *= s; v.y *= s; v.z *= s; v.w *= s;
        ((uint4*)dst)[i] = f2tf4(v);
    }
}

// ---------------------------------------------------------------------------
// Kernel 1: fused QKV projection, tf32 MMA, cp.async, 2 CTAs/SM.
// Block tile 128x64, warp tile 32x32 (4x2 warps).
// Epilogue stages results in smem (permutation applied at STS time), then
// writes global with contiguous STG.128 -- coalesced permuted layouts.
// ---------------------------------------------------------------------------
__global__ __launch_bounds__(256, 2)
void qkv_kernel()
{
    extern __shared__ unsigned smu[];
    unsigned* Xs = smu;             // [128][132]
    unsigned* Ws = smu + 128*132;   // [128][72]
    unsigned* Sg = smu;             // staging reuse: q/k [128][68], v [64][132]

    const int bx = blockIdx.x;     // 64-col tile (0..15)
    const int by = blockIdx.y;     // 128-row tile
    const int mat = blockIdx.z;
    const float* Wg = (mat == 0) ? g_wq : (mat == 1 ? g_wk : g_wv);
    float* outp     = (mat == 0) ? g_q  : (mat == 1 ? g_k  : g_v);

    const int tid = threadIdx.x;
    const int wid = tid >> 5, lane = tid & 31;
    const int g = lane >> 2, c = lane & 3;
    const int wm2 = wid >> 1, wn2 = wid & 1;

    // async loads: X [128x128], W [128x64]
    #pragma unroll
    for (int it = 0; it < 16; ++it) {
        int lin = it * 256 + tid;
        int m = lin >> 5, c4 = lin & 31;
        cpa16(saddr(Xs + m*132 + c4*4), g_x + (size_t)(by*128 + m)*128 + c4*4);
    }
    #pragma unroll
    for (int it = 0; it < 8; ++it) {
        int lin = it * 256 + tid;
        int k = lin >> 4, n4 = lin & 15;
        cpa16(saddr(Ws + k*72 + n4*4), Wg + (size_t)k*1024 + bx*64 + n4*4);
    }
    CP_COMMIT;
    CP_WAIT0;
    __syncthreads();

    float4 acc[2][4];
    #pragma unroll
    for (int i = 0; i < 2; ++i)
        #pragma unroll
        for (int j = 0; j < 4; ++j) acc[i][j] = make_float4(0.f, 0.f, 0.f, 0.f);

    #pragma unroll
    for (int k8 = 0; k8 < 16; ++k8) {
        int kk = k8 * 8;
        unsigned a[2][4];
        #pragma unroll
        for (int mt = 0; mt < 2; ++mt) {
            int r = wm2*32 + mt*16 + g;
            a[mt][0] = Xs[r*132 + kk + c];
            a[mt][1] = Xs[(r+8)*132 + kk + c];
            a[mt][2] = Xs[r*132 + kk + c + 4];
            a[mt][3] = Xs[(r+8)*132 + kk + c + 4];
        }
        #pragma unroll
        for (int nt = 0; nt < 4; ++nt) {
            unsigned b0 = Ws[(kk+c  )*72 + wn2*32 + nt*8 + g];
            unsigned b1 = Ws[(kk+c+4)*72 + wn2*32 + nt*8 + g];
            mma8(acc[0][nt], a[0][0], a[0][1], a[0][2], a[0][3], b0, b1);
            mma8(acc[1][nt], a[1][0], a[1][1], a[1][2], a[1][3], b0, b1);
        }
    }

    __syncthreads();   // done reading Xs/Ws; staging may overwrite

    const int hh = bx >> 1, h4 = bx & 1;

    if (mat < 2) {
        // stage [row][4 sections x 16 + pad=68]: posl(dl) = (dl%4)*16 + dl/4
        #pragma unroll
        for (int mt = 0; mt < 2; ++mt) {
            int r0 = wm2*32 + mt*16 + g;
            #pragma unroll
            for (int nt = 0; nt < 4; ++nt) {
                int dl = wn2*32 + nt*8 + 2*c;             // even
                int p0 = ((dl & 3) << 4) + (dl >> 2);
                int p1 = (((dl+1) & 3) << 4) + (dl >> 2); // dl+1 same >>2
                Sg[r0*68 + p0]     = f2tf(acc[mt][nt].x);
                Sg[r0*68 + p1]     = f2tf(acc[mt][nt].y);
                Sg[(r0+8)*68 + p0] = f2tf(acc[mt][nt].z);
                Sg[(r0+8)*68 + p1] = f2tf(acc[mt][nt].w);
            }
        }
        __syncthreads();
        // coalesced write-out: per row, 4 runs of 16 words at sec*32 + h4*16
        #pragma unroll
        for (int it = 0; it < 8; ++it) {
            int lin = it * 256 + tid;
            int m = lin >> 4, ch = lin & 15;
            uint4 v = *(const uint4*)(Sg + m*68 + ch*4);
            int mg = by*128 + m;
            int bbi = mg >> 11, t = mg & (T_ - 1);
            float* dst = outp + ((size_t)(bbi*H_ + hh)*T_ + t)*D_
                       + (ch >> 2)*32 + h4*16 + (ch & 3)*4;
            *(uint4*)dst = v;
        }
    } else {
        // V: stage transpose [dl 0..63][blk*64 + posk(kt)], stride 132
        unsigned* Vg = Sg;
        #pragma unroll
        for (int mt = 0; mt < 2; ++mt) {
            int t0  = wm2*32 + mt*16 + g;
            int blk = t0 >> 6, kt = t0 & 63;
            int p0  = ((kt & 3) << 4) + (kt >> 2);   // kt+8 -> p0+2
            #pragma unroll
            for (int nt = 0; nt < 4; ++nt) {
                int dl = wn2*32 + nt*8 + 2*c;
                Vg[dl*132     + blk*64 + p0]     = f2tf(acc[mt][nt].x);
                Vg[(dl+1)*132 + blk*64 + p0]     = f2tf(acc[mt][nt].y);
                Vg[dl*132     + blk*64 + p0 + 2] = f2tf(acc[mt][nt].z);
                Vg[(dl+1)*132 + blk*64 + p0 + 2] = f2tf(acc[mt][nt].w);
            }
        }
        __syncthreads();
        // coalesced write-out: per dl, two contiguous 64-word runs (per block)
        const int bbi = by >> 4;   // 128-row tile never crosses batch
        #pragma unroll
        for (int it = 0; it < 8; ++it) {
            int lin = it * 256 + tid;
            int dl = lin >> 5, ch = lin & 31;
            uint4 v = *(const uint4*)(Vg + dl*132 + ch*4);
            int blk = ch >> 4, pk = (ch & 15)*4;
            int nb  = (by & 15)*2 + blk;
            float* dst = g_v
                + (((size_t)((bbi*H_ + hh)*32 + nb))*128 + h4*64 + dl)*64 + pk;
            *(uint4*)dst = v;
        }
    }
}

// ---------------------------------------------------------------------------
// Kernel 2: causal flash attention, tf32 MMA, cp.async pipelined K/V,
// k-permuted smem layouts -> all fragment loads are LDS.128.
// Qs/Ks: [row][4 sections x 36 words]   (k-dim permuted, stride 144)
// Vst:   [d][4 sections x 20 words]     (key-dim permuted, stride 80)
// Ps:    [qrow][4 sections x 20 words]  (key-dim permuted, stride 80)
// ---------------------------------------------------------------------------
__global__ __launch_bounds__(256, 1)
void attn_kernel()
{
    extern __shared__ unsigned smu[];
    unsigned* Qs  = smu;                    // [128][144]
    unsigned* Ks  = Qs + 128*144;           // [ 64][144]
    unsigned* Vst = Ks +  64*144;           // [128][ 80]
    unsigned* Ps  = Vst + 128*80;           // [128][ 80]
    float*   red  = (float*)(Ps + 128*80);  // [128]

    const int bh    = blockIdx.y;
    const int qi    = (int)gridDim.x - 1 - (int)blockIdx.x;  // big tiles first
    const int qbase = qi * 128;
    const int tid   = threadIdx.x;
    const int wid   = tid >> 5, lane = tid & 31;
    const int g = lane >> 2, c = lane & 3;
    const int wbase = wid * 16;              // S-layout row base
    const int wm2 = wid >> 1, wn2 = wid & 1; // PV layout

    const float* qg = g_q + ((size_t)bh * T_ + qbase) * D_;
    const float* kg = g_k + (size_t)bh * T_ * D_;
    const float* vg = g_v + (size_t)bh * 32 * 128 * 64;  // [block][d][64]

    // prologue: Q, K0, V0 via cp.async (3 groups)
    #pragma unroll
    for (int it = 0; it < 16; ++it) {
        int lin = it * 256 + tid;
        int m = lin >> 5, ch = lin & 31;             // ch: 32 16B-chunks/row
        cpa16(saddr(Qs + m*144 + (ch>>3)*36 + (ch&7)*4), qg + m*128 + ch*4);
    }
    CP_COMMIT;
    #pragma unroll
    for (int it = 0; it < 8; ++it) {
        int lin = it * 256 + tid;
        int m = lin >> 5, ch = lin & 31;
        cpa16(saddr(Ks + m*144 + (ch>>3)*36 + (ch&7)*4), kg + m*128 + ch*4);
    }
    CP_COMMIT;
    #pragma unroll
    for (int it = 0; it < 8; ++it) {
        int lin = it * 256 + tid;
        int d = lin >> 4, ch = lin & 15;             // ch: 16 16B-chunks/row
        cpa16(saddr(Vst + d*80 + (ch>>2)*20 + (ch&3)*4), vg + d*64 + ch*4);
    }
    CP_COMMIT;
    CP_WAIT0;
    __syncthreads();

    float m0 = NEGINF, m1 = NEGINF, l0 = 0.f, l1 = 0.f;
    float4 oacc[2][8];
    #pragma unroll
    for (int i = 0; i < 2; ++i)
        #pragma unroll
        for (int j = 0; j < 8; ++j) oacc[i][j] = make_float4(0.f, 0.f, 0.f, 0.f);

    const int   ntiles = 2 * qi + 2;
    const float sscale = 0.088388347648318447f;   // 128^-0.5

    // per-thread fragment base offsets
    const unsigned* qA0 = Qs + (wbase+g  )*144 + c*36;
    const unsigned* qA1 = Qs + (wbase+g+8)*144 + c*36;

    for (int n = 0; n < ntiles; ++n) {
        const bool pre = (n + 1 < ntiles);

        // S = Q K^T : warp rows [wbase, wbase+16), all 64 cols
        float4 sacc[8];
        #pragma unroll
        for (int nt = 0; nt < 8; ++nt) sacc[nt] = make_float4(0.f, 0.f, 0.f, 0.f);

        #pragma unroll
        for (int kp = 0; kp < 8; ++kp) {        // 2 k8-steps per kp
            uint4 aL = *(const uint4*)(qA0 + 4*kp);
            uint4 aH = *(const uint4*)(qA1 + 4*kp);
            #pragma unroll
            for (int nt = 0; nt < 8; ++nt) {
                uint4 bb = *(const uint4*)(Ks + (nt*8+g)*144 + c*36 + 4*kp);
                mma8(sacc[nt], aL.x, aH.x, aL.y, aH.y, bb.x, bb.y);
                mma8(sacc[nt], aL.z, aH.z, aL.w, aH.w, bb.z, bb.w);
            }
        }
        __syncthreads();   // bar1: all warps done reading Ks

        // async-stage K_{n+1} (arrives during softmax+PV)
        if (pre) {
            const float* kt = kg + (size_t)(n+1) * 64 * D_;
            #pragma unroll
            for (int it = 0; it < 8; ++it) {
                int lin = it * 256 + tid;
                int m = lin >> 5, ch = lin & 31;
                cpa16(saddr(Ks + m*144 + (ch>>3)*36 + (ch&7)*4), kt + m*128 + ch*4);
            }
            CP_COMMIT;
        }

        // scale
        #pragma unroll
        for (int nt = 0; nt < 8; ++nt) {
            sacc[nt].x *= sscale; sacc[nt].y *= sscale;
            sacc[nt].z *= sscale; sacc[nt].w *= sscale;
        }
        // causal mask (only last two tiles can touch the diagonal)
        if (n >= 2 * qi) {
            int rg0 = qbase + wbase + g, rg1 = rg0 + 8;
            #pragma unroll
            for (int nt = 0; nt < 8; ++nt) {
                int c0 = n*64 + nt*8 + 2*c;
                if (c0     > rg0) sacc[nt].x = NEGINF;
                if (c0 + 1 > rg0) sacc[nt].y = NEGINF;
                if (c0     > rg1) sacc[nt].z = NEGINF;
                if (c0 + 1 > rg1) sacc[nt].w = NEGINF;
            }
        }

        // online softmax: rows r0 = wbase+g, r1 = r0+8 (4-lane group reduce)
        float mx0 = NEGINF, mx1 = NEGINF;
        #pragma unroll
        for (int nt = 0; nt < 8; ++nt) {
            mx0 = fmaxf(mx0, fmaxf(sacc[nt].x, sacc[nt].y));
            mx1 = fmaxf(mx1, fmaxf(sacc[nt].z, sacc[nt].w));
        }
        mx0 = fmaxf(mx0, __shfl_xor_sync(0xffffffffu, mx0, 1));
        mx0 = fmaxf(mx0, __shfl_xor_sync(0xffffffffu, mx0, 2));
        mx1 = fmaxf(mx1, __shfl_xor_sync(0xffffffffu, mx1, 1));
        mx1 = fmaxf(mx1, __shfl_xor_sync(0xffffffffu, mx1, 2));

        float mn0 = fmaxf(m0, mx0), mn1 = fmaxf(m1, mx1);
        float al0 = __expf(m0 - mn0), al1 = __expf(m1 - mn1);
        m0 = mn0; m1 = mn1;

        int r0 = wbase + g, r1 = r0 + 8;
        // Ps write offsets: col = nt*8+2c -> sec = (2c)&3 (x), (2c+1)&3 (y),
        // j = 2nt + (c>>1)
        unsigned* psx0 = Ps + r0*80 + ((2*c  )&3)*20 + (c>>1);
        unsigned* psy0 = Ps + r0*80 + ((2*c+1)&3)*20 + (c>>1);
        unsigned* psx1 = Ps + r1*80 + ((2*c  )&3)*20 + (c>>1);
        unsigned* psy1 = Ps + r1*80 + ((2*c+1)&3)*20 + (c>>1);
        float rs0 = 0.f, rs1 = 0.f;
        #pragma unroll
        for (int nt = 0; nt < 8; ++nt) {
            float px = __expf(sacc[nt].x - mn0);
            float py = __expf(sacc[nt].y - mn0);
            float pz = __expf(sacc[nt].z - mn1);
            float pw = __expf(sacc[nt].w - mn1);
            rs0 += px + py; rs1 += pz + pw;
            psx0[2*nt] = f2tf(px);  psy0[2*nt] = f2tf(py);
            psx1[2*nt] = f2tf(pz);  psy1[2*nt] = f2tf(pw);
        }
        rs0 += __shfl_xor_sync(0xffffffffu, rs0, 1);
        rs0 += __shfl_xor_sync(0xffffffffu, rs0, 2);
        rs1 += __shfl_xor_sync(0xffffffffu, rs1, 1);
        rs1 += __shfl_xor_sync(0xffffffffu, rs1, 2);
        l0 = l0 * al0 + rs0;
        l1 = l1 * al1 + rs1;
        if (c == 0) { red[r0] = al0; red[r1] = al1; }

        // ensure V_n arrived (oldest pending group); K_{n+1} may still fly
        if (pre) { CP_WAIT1; } else { CP_WAIT0; }
        __syncthreads();   // bar2: Ps + alpha + V_n visible

        // rescale O (PV layout rows: wm2*32 + mt*16 + {g, g+8})
        float af0 = red[wm2*32      + g], af1 = red[wm2*32      + g + 8];
        float af2 = red[wm2*32 + 16 + g], af3 = red[wm2*32 + 16 + g + 8];
        #pragma unroll
        for (int nt = 0; nt < 8; ++nt) {
            oacc[0][nt].x *= af0; oacc[0][nt].y *= af0;
            oacc[0][nt].z *= af1; oacc[0][nt].w *= af1;
            oacc[1][nt].x *= af2; oacc[1][nt].y *= af2;
            oacc[1][nt].z *= af3; oacc[1][nt].w *= af3;
        }

        // O += P @ V  (warp: 32 rows x 64 cols), vectorized fragments
        #pragma unroll
        for (int kp = 0; kp < 4; ++kp) {     // 2 k8-steps per kp
            uint4 pL0 = *(const uint4*)(Ps + (wm2*32   + g)*80 + c*20 + 4*kp);
            uint4 pH0 = *(const uint4*)(Ps + (wm2*32+ 8+ g)*80 + c*20 + 4*kp);
            uint4 pL1 = *(const uint4*)(Ps + (wm2*32+16+ g)*80 + c*20 + 4*kp);
            uint4 pH1 = *(const uint4*)(Ps + (wm2*32+24+ g)*80 + c*20 + 4*kp);
            #pragma unroll
            for (int nt = 0; nt < 8; ++nt) {
                uint4 bb = *(const uint4*)(Vst + (wn2*64+nt*8+g)*80 + c*20 + 4*kp);
                mma8(oacc[0][nt], pL0.x, pH0.x, pL0.y, pH0.y, bb.x, bb.y);
                mma8(oacc[0][nt], pL0.z, pH0.z, pL0.w, pH0.w, bb.z, bb.w);
                mma8(oacc[1][nt], pL1.x, pH1.x, pL1.y, pH1.y, bb.x, bb.y);
                mma8(oacc[1][nt], pL1.z, pH1.z, pL1.w, pH1.w, bb.z, bb.w);
            }
        }

        // ensure K_{n+1} arrived before next S reads Ks
        CP_WAIT0;
        __syncthreads();   // bar3: K_{n+1} visible; Vst free

        // async-stage V_{n+1} (arrives during next S + softmax)
        if (pre) {
            const float* vt = vg + (size_t)(n+1) * 128 * 64;
            #pragma unroll
            for (int it = 0; it < 8; ++it) {
                int lin = it * 256 + tid;
                int d = lin >> 4, ch = lin & 15;
                cpa16(saddr(Vst + d*80 + (ch>>2)*20 + (ch&3)*4), vt + d*64 + ch*4);
            }
            CP_COMMIT;
        }
    }

    // final normalization: pass l across layouts via smem
    __syncthreads();
    if (c == 0) { red[wbase + g] = l0; red[wbase + g + 8] = l1; }
    __syncthreads();
    float inv0 = 1.f / red[wm2*32      + g], inv1 = 1.f / red[wm2*32      + g + 8];
    float inv2 = 1.f / red[wm2*32 + 16 + g], inv3 = 1.f / red[wm2*32 + 16 + g + 8];

    // outputs tf32-rounded so proj can raw-copy them (g_ao stays linear)
    const int bb = bh >> 3, hh = bh & 7;
    #pragma unroll
    for (int mt = 0; mt < 2; ++mt) {
        float iv0 = (mt == 0) ? inv0 : inv2;
        float iv1 = (mt == 0) ? inv1 : inv3;
        int t0 = qbase + wm2*32 + mt*16 + g;
        #pragma unroll
        for (int nt = 0; nt < 8; ++nt) {
            int d = wn2*64 + nt*8 + 2*c;
            float* p0 = g_ao + ((size_t)(bb*T_ + t0))*(H_*D_) + hh*128 + d;
            *(float2*)p0 = make_float2(f2tff(oacc[mt][nt].x * iv0),
                                       f2tff(oacc[mt][nt].y * iv0));
            float* p1 = g_ao + ((size_t)(bb*T_ + t0 + 8))*(H_*D_) + hh*128 + d;
            *(float2*)p1 = make_float2(f2tff(oacc[mt][nt].z * iv1),
                                       f2tff(oacc[mt][nt].w * iv1));
        }
    }
}

// ---------------------------------------------------------------------------
// Kernel 3: output projection, tf32 MMA, register double-buffered k-chunks.
// ---------------------------------------------------------------------------
__global__ __launch_bounds__(256, 1)
void proj_kernel(const float* __restrict__ bu, float* __restrict__ out)
{
    extern __shared__ unsigned smu[];
    unsigned* As = smu;           // [64][68]
    unsigned* Bs = smu + 64*68;   // [64][136]

    const int by  = blockIdx.x;
    const int tid = threadIdx.x;
    const int wid = tid >> 5, lane = tid & 31;
    const int g = lane >> 2, c = lane & 3;
    const int wm = wid >> 1, wn = wid & 1;

    float4 acc[8];
    #pragma unroll
    for (int j = 0; j < 8; ++j) acc[j] = make_float4(0.f, 0.f, 0.f, 0.f);

    float4 areg[4], breg[8];
    #pragma unroll
    for (int it = 0; it < 4; ++it) {
        int lin = it * 256 + tid;
        int m = lin >> 4, c4 = lin & 15;
        areg[it] = *(const float4*)(g_ao + (size_t)(by*64 + m)*1024 + c4*4);
    }
    #pragma unroll
    for (int it = 0; it < 8; ++it) {
        int lin = it * 256 + tid;
        int k = lin >> 5, n4 = lin & 31;
        breg[it] = *(const float4*)(g_wu + (size_t)k*128 + n4*4);
    }

    for (int kc = 0; kc < 16; ++kc) {
        __syncthreads();
        #pragma unroll
        for (int it = 0; it < 4; ++it) {
            int lin = it * 256 + tid;
            int m = lin >> 4, c4 = lin & 15;
            *(uint4*)(As + m*68 + c4*4) = f4bits(areg[it]);
        }
        #pragma unroll
        for (int it = 0; it < 8; ++it) {
            int lin = it * 256 + tid;
            int k = lin >> 5, n4 = lin & 31;
            *(uint4*)(Bs + k*136 + n4*4) = f4bits(breg[it]);
        }
        __syncthreads();

        if (kc < 15) {
            #pragma unroll
            for (int it = 0; it < 4; ++it) {
                int lin = it * 256 + tid;
                int m = lin >> 4, c4 = lin & 15;
                areg[it] = *(const float4*)(g_ao + (size_t)(by*64 + m)*1024
                                                 + (kc+1)*64 + c4*4);
            }
            #pragma unroll
            for (int it = 0; it < 8; ++it) {
                int lin = it * 256 + tid;
                int k = lin >> 5, n4 = lin & 31;
                breg[it] = *(const float4*)(g_wu + (size_t)((kc+1)*64 + k)*128 + n4*4);
            }
        }

        #pragma unroll
        for (int k8 = 0; k8 < 8; ++k8) {
            int kk = k8 * 8;
            int r = wm*16 + g;
            unsigned a0 = As[r*68 + kk + c];
            unsigned a1 = As[(r+8)*68 + kk + c];
            unsigned a2 = As[r*68 + kk + c + 4];
            unsigned a3 = As[(r+8)*68 + kk + c + 4];
            #pragma unroll
            for (int nt = 0; nt < 8; ++nt) {
                unsigned b0 = Bs[(kk+c  )*136 + wn*64 + nt*8 + g];
                unsigned b1 = Bs[(kk+c+4)*136 + wn*64 + nt*8 + g];
                mma8(acc[nt], a0, a1, a2, a3, b0, b1);
            }
        }
    }

    #pragma unroll
    for (int nt = 0; nt < 8; ++nt) {
        int d = wn*64 + nt*8 + 2*c;
        float bv0 = bu[d], bv1 = bu[d + 1];
        int m0 = by*64 + wm*16 + g;
        *(float2*)(out + (size_t)m0*128 + d) =
            make_float2(acc[nt].x + bv0, acc[nt].y + bv1);
        *(float2*)(out + (size_t)(m0 + 8)*128 + d) =
            make_float2(acc[nt].z + bv0, acc[nt].w + bv1);
    }
}

// ---------------------------------------------------------------------------
extern "C" void kernel_launch(void* const* d_in, const int* in_sizes, int n_in,
                              void* d_out, int out_size)
{
    const float* x  = (const float*)d_in[0];
    const float* Wq = (const float*)d_in[1];
    const float* Wk = (const float*)d_in[2];
    const float* Wv = (const float*)d_in[3];
    const float* Wu = (const float*)d_in[4];
    const float* bu = (const float*)d_in[5];
    float* out = (float*)d_out;

    const int SMEM1 = (128*132 + 128*72) * (int)sizeof(unsigned);                  // 104448
    const int SMEM2 = (128*144 + 64*144 + 128*80 + 128*80 + 128) * (int)sizeof(unsigned); // 193024
    const int SMEM3 = (64*68 + 64*136) * (int)sizeof(unsigned);                    // 52224

    cudaFuncSetAttribute(qkv_kernel,  cudaFuncAttributeMaxDynamicSharedMemorySize, SMEM1);
    cudaFuncSetAttribute(attn_kernel, cudaFuncAttributeMaxDynamicSharedMemorySize, SMEM2);
    cudaFuncSetAttribute(proj_kernel, cudaFuncAttributeMaxDynamicSharedMemorySize, SMEM3);

    prep_kernel<<<dim3(128, 5), 256>>>(x, Wq, Wk, Wv, Wu);
    qkv_kernel<<<dim3(16, 64, 3), 256, SMEM1>>>();
    attn_kernel<<<dim3(16, 32), 256, SMEM2>>>();
    proj_kernel<<<dim3(128), 256, SMEM3>>>(bu, out);
}

// round 15
// speedup vs baseline: 1.8541x; 1.1158x over previous
#include <cuda_runtime.h>
#include <math.h>
#include <stdint.h>

#define B_  4
#define T_  2048
#define D_  128
#define H_  8
#define BH_ (B_*H_)
#define NEGINF (-1e30f)

// scratch (device globals -- no allocation allowed); all layouts LINEAR
__device__ float g_q [BH_*T_*D_];
__device__ float g_k [BH_*T_*D_];
__device__ float g_v [BH_*T_*D_];
__device__ float g_ao[B_*T_*H_*D_];
// pre-rounded tf32 operands
__device__ float g_x [B_*T_*D_];
__device__ float g_wq[D_*H_*D_];
__device__ float g_wk[D_*H_*D_];
__device__ float g_wv[D_*H_*D_];
__device__ float g_wu[H_*D_*D_];

__device__ __forceinline__ unsigned f2tf(float f){
    unsigned u; asm("cvt.rna.tf32.f32 %0, %1;" : "=r"(u) : "f"(f)); return u;
}
__device__ __forceinline__ float f2tff(float f){
    return __uint_as_float(f2tf(f));
}
__device__ __forceinline__ uint4 f2tf4(float4 v){
    return make_uint4(f2tf(v.x), f2tf(v.y), f2tf(v.z), f2tf(v.w));
}
__device__ __forceinline__ uint4 f4bits(float4 v){
    return make_uint4(__float_as_uint(v.x), __float_as_uint(v.y),
                      __float_as_uint(v.z), __float_as_uint(v.w));
}
__device__ __forceinline__ uint32_t saddr(const void* p){
    return (uint32_t)__cvta_generic_to_shared(p);
}
__device__ __forceinline__ void cpa16(uint32_t dst, const void* src){
    asm volatile("cp.async.cg.shared.global [%0], [%1], 16;" :: "r"(dst), "l"(src));
}
#define CP_COMMIT  asm volatile("cp.async.commit_group;")
#define CP_WAIT0   asm volatile("cp.async.wait_group 0;")
#define CP_WAIT1   asm volatile("cp.async.wait_group 1;")

// named barriers
#define NBAR_SYNC_256(id)   asm volatile("bar.sync %0, 256;"   :: "r"(id) : "memory")
#define NBAR_ARRIVE_256(id) asm volatile("bar.arrive %0, 256;" :: "r"(id) : "memory")
#define NBAR_SYNC_128(id)   asm volatile("bar.sync %0, 128;"   :: "r"(id) : "memory")

__device__ __forceinline__ void mma8(float4& d,
    unsigned a0, unsigned a1, unsigned a2, unsigned a3,
    unsigned b0, unsigned b1)
{
    asm volatile(
        "mma.sync.aligned.m16n8k8.row.col.f32.tf32.tf32.f32 "
        "{%0,%1,%2,%3},{%4,%5,%6,%7},{%8,%9},{%0,%1,%2,%3};"
        : "+f"(d.x), "+f"(d.y), "+f"(d.z), "+f"(d.w)
        : "r"(a0), "r"(a1), "r"(a2), "r"(a3), "r"(b0), "r"(b1));
}

// ---------------------------------------------------------------------------
// Kernel 0: pre-round inputs to tf32 (Wv gets 128^-0.25 baked in).
// ---------------------------------------------------------------------------
__global__ __launch_bounds__(256, 4)
void prep_kernel(const float* __restrict__ x,  const float* __restrict__ wq,
                 const float* __restrict__ wk, const float* __restrict__ wv,
                 const float* __restrict__ wu)
{
    const int seg = blockIdx.y;
    const float* src; float* dst; int n4; float s = 1.0f;
    if      (seg == 0) { src = x;  dst = g_x;  n4 = (B_*T_*D_)/4; }
    else if (seg == 1) { src = wq; dst = g_wq; n4 = (D_*H_*D_)/4; }
    else if (seg == 2) { src = wk; dst = g_wk; n4 = (D_*H_*D_)/4; }
    else if (seg == 3) { src = wv; dst = g_wv; n4 = (D_*H_*D_)/4; s = 0.29730177875068026f; }
    else               { src = wu; dst = g_wu; n4 = (H_*D_*D_)/4; }

    for (int i = blockIdx.x * blockDim.x + threadIdx.x; i < n4;
         i += gridDim.x * blockDim.x) {
        float4 v = ((const float4*)src)[i];
        v.x *= s; v.y *= s; v.z *= s; v.w *= s;
        ((uint4*)dst)[i] = f2tf4(v);
    }
}

// ---------------------------------------------------------------------------
// Kernel 1: fused QKV projection, tf32 MMA, cp.async, 2 CTAs/SM.  (round-11)
// Block tile 128x64, warp tile 32x32 (4x2 warps).  Linear outputs.
// ---------------------------------------------------------------------------
__global__ __launch_bounds__(256, 2)
void qkv_kernel()
{
    extern __shared__ unsigned smu[];
    unsigned* Xs = smu;             // [128][132]
    unsigned* Ws = smu + 128*132;   // [128][72]

    const int bx = blockIdx.x;     // 64-col tile (0..15)
    const int by = blockIdx.y;     // 128-row tile
    const int mat = blockIdx.z;
    const float* Wg = (mat == 0) ? g_wq : (mat == 1 ? g_wk : g_wv);
    float* outp     = (mat == 0) ? g_q  : (mat == 1 ? g_k  : g_v);

    const int tid = threadIdx.x;
    const int wid = tid >> 5, lane = tid & 31;
    const int g = lane >> 2, c = lane & 3;
    const int wm2 = wid >> 1, wn2 = wid & 1;

    #pragma unroll
    for (int it = 0; it < 16; ++it) {
        int lin = it * 256 + tid;
        int m = lin >> 5, c4 = lin & 31;
        cpa16(saddr(Xs + m*132 + c4*4), g_x + (size_t)(by*128 + m)*128 + c4*4);
    }
    #pragma unroll
    for (int it = 0; it < 8; ++it) {
        int lin = it * 256 + tid;
        int k = lin >> 4, n4 = lin & 15;
        cpa16(saddr(Ws + k*72 + n4*4), Wg + (size_t)k*1024 + bx*64 + n4*4);
    }
    CP_COMMIT;
    CP_WAIT0;
    __syncthreads();

    float4 acc[2][4];
    #pragma unroll
    for (int i = 0; i < 2; ++i)
        #pragma unroll
        for (int j = 0; j < 4; ++j) acc[i][j] = make_float4(0.f, 0.f, 0.f, 0.f);

    #pragma unroll
    for (int k8 = 0; k8 < 16; ++k8) {
        int kk = k8 * 8;
        unsigned a[2][4];
        #pragma unroll
        for (int mt = 0; mt < 2; ++mt) {
            int r = wm2*32 + mt*16 + g;
            a[mt][0] = Xs[r*132 + kk + c];
            a[mt][1] = Xs[(r+8)*132 + kk + c];
            a[mt][2] = Xs[r*132 + kk + c + 4];
            a[mt][3] = Xs[(r+8)*132 + kk + c + 4];
        }
        #pragma unroll
        for (int nt = 0; nt < 4; ++nt) {
            unsigned b0 = Ws[(kk+c  )*72 + wn2*32 + nt*8 + g];
            unsigned b1 = Ws[(kk+c+4)*72 + wn2*32 + nt*8 + g];
            mma8(acc[0][nt], a[0][0], a[0][1], a[0][2], a[0][3], b0, b1);
            mma8(acc[1][nt], a[1][0], a[1][1], a[1][2], a[1][3], b0, b1);
        }
    }

    const int hh = bx >> 1;
    #pragma unroll
    for (int mt = 0; mt < 2; ++mt) {
        int mg0 = by*128 + wm2*32 + mt*16 + g;
        int b0i = mg0 >> 11, t0 = mg0 & (T_ - 1);
        int mg1 = mg0 + 8;
        int b1i = mg1 >> 11, t1 = mg1 & (T_ - 1);
        #pragma unroll
        for (int nt = 0; nt < 4; ++nt) {
            int d = ((bx & 1)*64 + wn2*32 + nt*8 + 2*c);
            float* p0 = outp + ((size_t)(b0i*H_ + hh)*T_ + t0)*D_ + d;
            *(float2*)p0 = make_float2(f2tff(acc[mt][nt].x), f2tff(acc[mt][nt].y));
            float* p1 = outp + ((size_t)(b1i*H_ + hh)*T_ + t1)*D_ + d;
            *(float2*)p1 = make_float2(f2tff(acc[mt][nt].z), f2tff(acc[mt][nt].w));
        }
    }
}

// ---------------------------------------------------------------------------
// Kernel 2: causal flash attention, WARP-SPECIALIZED, tf32 MMA, cp.async.
// grid (32 q-tiles, 32 bh), 256 threads.  BM=64 queries, BN=64 keys/tile.
// A-group (warps 0-3): S = Q K^T + online softmax, produces Ps/alpha.
// B-group (warps 4-7): O += P V, consumes Ps/alpha one tile behind.
// Ks/Vs/Ps/alpha double-buffered.  K staged by A (distance 2), V by B.
// Sync: FULL (A->B) ids {1,5} by tile parity; FREE (B->A) ids {2,6};
// A-internal id 3 (128); B-internal id 4 (128).
// ---------------------------------------------------------------------------
__global__ __launch_bounds__(256, 1)
void attn_kernel()
{
    extern __shared__ unsigned smu[];
    unsigned* Qs  = smu;                      // [64][132]
    unsigned* Ks  = smu + 64*132;             // [2][64][132]
    unsigned* Vs  = Ks + 2*64*132;            // [2][64][136]
    unsigned* Ps  = Vs + 2*64*136;            // [2][64][68]
    float* alphas = (float*)(Ps + 2*64*68);   // [2][64]
    float* lfin   = alphas + 2*64;            // [64]

    const int bh    = blockIdx.y;
    const int qi    = (int)gridDim.x - 1 - (int)blockIdx.x;  // big tiles first
    const int qbase = qi * 64;
    const int tid   = threadIdx.x;
    const int wid   = tid >> 5, lane = tid & 31;
    const int g = lane >> 2, c = lane & 3;
    const bool isA  = (wid < 4);
    const int  aw   = wid & 3;        // row-group index within each group
    const int  ltid = tid & 127;      // thread index within group
    const int  wb   = aw * 16;        // row base (both groups use 16-row tiles)

    const float* qg = g_q + ((size_t)bh * T_ + qbase) * D_;
    const float* kg = g_k + (size_t)bh * T_ * D_;
    const float* vg = g_v + (size_t)bh * T_ * D_;

    const int   ntiles = qi + 1;
    const float sscale = 0.088388347648318447f;   // 128^-0.5

    // ---- prologue loads (each group issues/commits/waits its OWN groups) ----
    if (isA) {
        #pragma unroll
        for (int it = 0; it < 16; ++it) {
            int lin = it*128 + ltid;
            int m = lin >> 5, ch = lin & 31;
            cpa16(saddr(Qs + m*132 + ch*4), qg + m*128 + ch*4);
        }
        CP_COMMIT;
        #pragma unroll
        for (int it = 0; it < 16; ++it) {
            int lin = it*128 + ltid;
            int m = lin >> 5, ch = lin & 31;
            cpa16(saddr(Ks + m*132 + ch*4), kg + m*128 + ch*4);
        }
        CP_COMMIT;
        if (ntiles > 1) {
            #pragma unroll
            for (int it = 0; it < 16; ++it) {
                int lin = it*128 + ltid;
                int m = lin >> 5, ch = lin & 31;
                cpa16(saddr(Ks + 64*132 + m*132 + ch*4), kg + (64 + m)*128 + ch*4);
            }
            CP_COMMIT;
        }
    } else {
        #pragma unroll
        for (int it = 0; it < 16; ++it) {
            int lin = it*128 + ltid;
            int m = lin >> 5, ch = lin & 31;
            cpa16(saddr(Vs + m*136 + ch*4), vg + m*128 + ch*4);
        }
        CP_COMMIT;
        if (ntiles > 1) {
            #pragma unroll
            for (int it = 0; it < 16; ++it) {
                int lin = it*128 + ltid;
                int m = lin >> 5, ch = lin & 31;
                cpa16(saddr(Vs + 64*136 + m*136 + ch*4), vg + (64 + m)*128 + ch*4);
            }
            CP_COMMIT;
        }
    }

    // persistent state
    float m0 = NEGINF, m1 = NEGINF, l0 = 0.f, l1 = 0.f;   // A
    float4 oacc[16];                                       // B
    if (!isA) {
        #pragma unroll
        for (int j = 0; j < 16; ++j) oacc[j] = make_float4(0.f, 0.f, 0.f, 0.f);
    }

    for (int j = 0; j <= ntiles; ++j) {
        if (isA) {
            if (j < ntiles) {
                // K_j must be arrived + visible within A
                if (j + 1 <= ntiles - 1) { CP_WAIT1; } else { CP_WAIT0; }
                NBAR_SYNC_128(3);

                const unsigned* Kb = Ks + (j & 1)*64*132;
                float4 sacc[8];
                #pragma unroll
                for (int nt = 0; nt < 8; ++nt) sacc[nt] = make_float4(0.f,0.f,0.f,0.f);

                #pragma unroll
                for (int k8 = 0; k8 < 16; ++k8) {
                    int kk = k8 * 8;
                    unsigned a0 = Qs[(wb+g  )*132 + kk + c];
                    unsigned a1 = Qs[(wb+g+8)*132 + kk + c];
                    unsigned a2 = Qs[(wb+g  )*132 + kk + c + 4];
                    unsigned a3 = Qs[(wb+g+8)*132 + kk + c + 4];
                    #pragma unroll
                    for (int nt = 0; nt < 8; ++nt) {
                        unsigned b0 = Kb[(nt*8+g)*132 + kk + c];
                        unsigned b1 = Kb[(nt*8+g)*132 + kk + c + 4];
                        mma8(sacc[nt], a0, a1, a2, a3, b0, b1);
                    }
                }
                NBAR_SYNC_128(3);   // all A done reading Ks[j&1]
                if (j + 2 <= ntiles - 1) {   // stage K_{j+2} into freed buffer
                    const float* kt = kg + (size_t)(j+2) * 64 * D_;
                    unsigned* Kd = Ks + (j & 1)*64*132;
                    #pragma unroll
                    for (int it = 0; it < 16; ++it) {
                        int lin = it*128 + ltid;
                        int m = lin >> 5, ch = lin & 31;
                        cpa16(saddr(Kd + m*132 + ch*4), kt + m*128 + ch*4);
                    }
                    CP_COMMIT;
                }

                // scale + causal mask (diagonal only in last tile)
                #pragma unroll
                for (int nt = 0; nt < 8; ++nt) {
                    sacc[nt].x *= sscale; sacc[nt].y *= sscale;
                    sacc[nt].z *= sscale; sacc[nt].w *= sscale;
                }
                if (j == ntiles - 1) {
                    int rg0 = qbase + wb + g, rg1 = rg0 + 8;
                    #pragma unroll
                    for (int nt = 0; nt < 8; ++nt) {
                        int c0 = j*64 + nt*8 + 2*c;
                        if (c0     > rg0) sacc[nt].x = NEGINF;
                        if (c0 + 1 > rg0) sacc[nt].y = NEGINF;
                        if (c0     > rg1) sacc[nt].z = NEGINF;
                        if (c0 + 1 > rg1) sacc[nt].w = NEGINF;
                    }
                }

                // row max (4-lane group reduce)
                float mx0 = NEGINF, mx1 = NEGINF;
                #pragma unroll
                for (int nt = 0; nt < 8; ++nt) {
                    mx0 = fmaxf(mx0, fmaxf(sacc[nt].x, sacc[nt].y));
                    mx1 = fmaxf(mx1, fmaxf(sacc[nt].z, sacc[nt].w));
                }
                mx0 = fmaxf(mx0, __shfl_xor_sync(0xffffffffu, mx0, 1));
                mx0 = fmaxf(mx0, __shfl_xor_sync(0xffffffffu, mx0, 2));
                mx1 = fmaxf(mx1, __shfl_xor_sync(0xffffffffu, mx1, 1));
                mx1 = fmaxf(mx1, __shfl_xor_sync(0xffffffffu, mx1, 2));

                float mn0 = fmaxf(m0, mx0), mn1 = fmaxf(m1, mx1);
                float al0 = __expf(m0 - mn0), al1 = __expf(m1 - mn1);
                m0 = mn0; m1 = mn1;

                // wait FREE: Ps[j&1]/alphas[j&1] free (B finished PV_{j-2})
                if (j >= 1) {
                    if ((j - 1) & 1) { NBAR_SYNC_256(6); } else { NBAR_SYNC_256(2); }
                }

                unsigned* Pb = Ps + (j & 1)*64*68;
                int r0 = wb + g, r1 = r0 + 8;
                float rs0 = 0.f, rs1 = 0.f;
                #pragma unroll
                for (int nt = 0; nt < 8; ++nt) {
                    float px = __expf(sacc[nt].x - mn0);
                    float py = __expf(sacc[nt].y - mn0);
                    float pz = __expf(sacc[nt].z - mn1);
                    float pw = __expf(sacc[nt].w - mn1);
                    rs0 += px + py; rs1 += pz + pw;
                    *(uint2*)&Pb[r0*68 + nt*8 + 2*c] = make_uint2(f2tf(px), f2tf(py));
                    *(uint2*)&Pb[r1*68 + nt*8 + 2*c] = make_uint2(f2tf(pz), f2tf(pw));
                }
                rs0 += __shfl_xor_sync(0xffffffffu, rs0, 1);
                rs0 += __shfl_xor_sync(0xffffffffu, rs0, 2);
                rs1 += __shfl_xor_sync(0xffffffffu, rs1, 1);
                rs1 += __shfl_xor_sync(0xffffffffu, rs1, 2);
                l0 = l0 * al0 + rs0;
                l1 = l1 * al1 + rs1;
                if (c == 0) {
                    alphas[(j & 1)*64 + r0] = al0;
                    alphas[(j & 1)*64 + r1] = al1;
                }
                // signal FULL: Ps_j / alpha_j ready
                if (j & 1) { NBAR_ARRIVE_256(5); } else { NBAR_ARRIVE_256(1); }
            }
        } else {
            if (j >= 1) {
                const int jj = j - 1;   // tile being consumed
                // V_jj must be arrived + visible within B
                if (j <= ntiles - 1) { CP_WAIT1; } else { CP_WAIT0; }
                NBAR_SYNC_128(4);
                // wait FULL: Ps_jj / alpha_jj ready
                if (jj & 1) { NBAR_SYNC_256(5); } else { NBAR_SYNC_256(1); }

                float af0 = alphas[(jj & 1)*64 + wb + g];
                float af1 = alphas[(jj & 1)*64 + wb + 8 + g];
                #pragma unroll
                for (int nt = 0; nt < 16; ++nt) {
                    oacc[nt].x *= af0; oacc[nt].y *= af0;
                    oacc[nt].z *= af1; oacc[nt].w *= af1;
                }

                const unsigned* Pb = Ps + (jj & 1)*64*68;
                const unsigned* Vb = Vs + (jj & 1)*64*136;
                #pragma unroll
                for (int k8 = 0; k8 < 8; ++k8) {
                    int kk = k8 * 8;
                    int r = wb + g;
                    unsigned a0 = Pb[r*68 + kk + c];
                    unsigned a1 = Pb[(r+8)*68 + kk + c];
                    unsigned a2 = Pb[r*68 + kk + c + 4];
                    unsigned a3 = Pb[(r+8)*68 + kk + c + 4];
                    #pragma unroll
                    for (int nt = 0; nt < 16; ++nt) {
                        unsigned b0 = Vb[(kk+c  )*136 + nt*8 + g];
                        unsigned b1 = Vb[(kk+c+4)*136 + nt*8 + g];
                        mma8(oacc[nt], a0, a1, a2, a3, b0, b1);
                    }
                }
                NBAR_SYNC_128(4);   // all B done reading Vs[jj&1], Ps[jj&1]
                if (j + 1 <= ntiles - 1) {  // stage V_{j+1} into freed buffer
                    const float* vt = vg + (size_t)(j+1) * 64 * D_;
                    unsigned* Vd = Vs + ((j+1) & 1)*64*136;
                    #pragma unroll
                    for (int it = 0; it < 16; ++it) {
                        int lin = it*128 + ltid;
                        int m = lin >> 5, ch = lin & 31;
                        cpa16(saddr(Vd + m*136 + ch*4), vt + m*128 + ch*4);
                    }
                    CP_COMMIT;
                }
                // signal FREE (Ps[jj&1] consumed), paired with A's sync at j+1
                if (j <= ntiles - 2) {
                    if (j & 1) { NBAR_ARRIVE_256(6); } else { NBAR_ARRIVE_256(2); }
                }
            } else {
                // j == 0 pre-credit so A@1 doesn't block
                if (ntiles >= 2) { NBAR_ARRIVE_256(2); }
            }
        }
    }

    // ---- epilogue: A publishes l; B normalizes and writes O ----
    if (isA && c == 0) {
        lfin[wb + g]     = l0;
        lfin[wb + g + 8] = l1;
    }
    __syncthreads();
    if (!isA) {
        float inv0 = 1.f / lfin[wb + g];
        float inv1 = 1.f / lfin[wb + 8 + g];
        const int bb = bh >> 3, hh = bh & 7;
        int t0 = qbase + wb + g;
        #pragma unroll
        for (int nt = 0; nt < 16; ++nt) {
            int d = nt*8 + 2*c;
            float* p0 = g_ao + ((size_t)(bb*T_ + t0))*(H_*D_) + hh*128 + d;
            *(float2*)p0 = make_float2(f2tff(oacc[nt].x * inv0),
                                       f2tff(oacc[nt].y * inv0));
            float* p1 = g_ao + ((size_t)(bb*T_ + t0 + 8))*(H_*D_) + hh*128 + d;
            *(float2*)p1 = make_float2(f2tff(oacc[nt].z * inv1),
                                       f2tff(oacc[nt].w * inv1));
        }
    }
}

// ---------------------------------------------------------------------------
// Kernel 3: output projection, tf32 MMA, register double-buffered k-chunks.
// ---------------------------------------------------------------------------
__global__ __launch_bounds__(256, 1)
void proj_kernel(const float* __restrict__ bu, float* __restrict__ out)
{
    extern __shared__ unsigned smu[];
    unsigned* As = smu;           // [64][68]
    unsigned* Bs = smu + 64*68;   // [64][136]

    const int by  = blockIdx.x;
    const int tid = threadIdx.x;
    const int wid = tid >> 5, lane = tid & 31;
    const int g = lane >> 2, c = lane & 3;
    const int wm = wid >> 1, wn = wid & 1;

    float4 acc[8];
    #pragma unroll
    for (int j = 0; j < 8; ++j) acc[j] = make_float4(0.f, 0.f, 0.f, 0.f);

    float4 areg[4], breg[8];
    #pragma unroll
    for (int it = 0; it < 4; ++it) {
        int lin = it * 256 + tid;
        int m = lin >> 4, c4 = lin & 15;
        areg[it] = *(const float4*)(g_ao + (size_t)(by*64 + m)*1024 + c4*4);
    }
    #pragma unroll
    for (int it = 0; it < 8; ++it) {
        int lin = it * 256 + tid;
        int k = lin >> 5, n4 = lin & 31;
        breg[it] = *(const float4*)(g_wu + (size_t)k*128 + n4*4);
    }

    for (int kc = 0; kc < 16; ++kc) {
        __syncthreads();
        #pragma unroll
        for (int it = 0; it < 4; ++it) {
            int lin = it * 256 + tid;
            int m = lin >> 4, c4 = lin & 15;
            *(uint4*)(As + m*68 + c4*4) = f4bits(areg[it]);
        }
        #pragma unroll
        for (int it = 0; it < 8; ++it) {
            int lin = it * 256 + tid;
            int k = lin >> 5, n4 = lin & 31;
            *(uint4*)(Bs + k*136 + n4*4) = f4bits(breg[it]);
        }
        __syncthreads();

        if (kc < 15) {
            #pragma unroll
            for (int it = 0; it < 4; ++it) {
                int lin = it * 256 + tid;
                int m = lin >> 4, c4 = lin & 15;
                areg[it] = *(const float4*)(g_ao + (size_t)(by*64 + m)*1024
                                                 + (kc+1)*64 + c4*4);
            }
            #pragma unroll
            for (int it = 0; it < 8; ++it) {
                int lin = it * 256 + tid;
                int k = lin >> 5, n4 = lin & 31;
                breg[it] = *(const float4*)(g_wu + (size_t)((kc+1)*64 + k)*128 + n4*4);
            }
        }

        #pragma unroll
        for (int k8 = 0; k8 < 8; ++k8) {
            int kk = k8 * 8;
            int r = wm*16 + g;
            unsigned a0 = As[r*68 + kk + c];
            unsigned a1 = As[(r+8)*68 + kk + c];
            unsigned a2 = As[r*68 + kk + c + 4];
            unsigned a3 = As[(r+8)*68 + kk + c + 4];
            #pragma unroll
            for (int nt = 0; nt < 8; ++nt) {
                unsigned b0 = Bs[(kk+c  )*136 + wn*64 + nt*8 + g];
                unsigned b1 = Bs[(kk+c+4)*136 + wn*64 + nt*8 + g];
                mma8(acc[nt], a0, a1, a2, a3, b0, b1);
            }
        }
    }

    #pragma unroll
    for (int nt = 0; nt < 8; ++nt) {
        int d = wn*64 + nt*8 + 2*c;
        float bv0 = bu[d], bv1 = bu[d + 1];
        int m0 = by*64 + wm*16 + g;
        *(float2*)(out + (size_t)m0*128 + d) =
            make_float2(acc[nt].x + bv0, acc[nt].y + bv1);
        *(float2*)(out + (size_t)(m0 + 8)*128 + d) =
            make_float2(acc[nt].z + bv0, acc[nt].w + bv1);
    }
}

// ---------------------------------------------------------------------------
extern "C" void kernel_launch(void* const* d_in, const int* in_sizes, int n_in,
                              void* d_out, int out_size)
{
    const float* x  = (const float*)d_in[0];
    const float* Wq = (const float*)d_in[1];
    const float* Wk = (const float*)d_in[2];
    const float* Wv = (const float*)d_in[3];
    const float* Wu = (const float*)d_in[4];
    const float* bu = (const float*)d_in[5];
    float* out = (float*)d_out;

    const int SMEM1 = (128*132 + 128*72) * (int)sizeof(unsigned);   // 104448
    const int SMEM2 = (64*132 + 2*64*132 + 2*64*136 + 2*64*68 + 192)
                      * (int)sizeof(unsigned);                      // 206592
    const int SMEM3 = (64*68 + 64*136) * (int)sizeof(unsigned);     // 52224

    cudaFuncSetAttribute(qkv_kernel,  cudaFuncAttributeMaxDynamicSharedMemorySize, SMEM1);
    cudaFuncSetAttribute(attn_kernel, cudaFuncAttributeMaxDynamicSharedMemorySize, SMEM2);
    cudaFuncSetAttribute(proj_kernel, cudaFuncAttributeMaxDynamicSharedMemorySize, SMEM3);

    prep_kernel<<<dim3(128, 5), 256>>>(x, Wq, Wk, Wv, Wu);
    qkv_kernel<<<dim3(16, 64, 3), 256, SMEM1>>>();
    attn_kernel<<<dim3(32, 32), 256, SMEM2>>>();
    proj_kernel<<<dim3(128), 256, SMEM3>>>(bu, out);
}

// round 16
// speedup vs baseline: 1.9538x; 1.0538x over previous
#include <cuda_runtime.h>
#include <math.h>
#include <stdint.h>

#define B_  4
#define T_  2048
#define D_  128
#define H_  8
#define BH_ (B_*H_)
#define NEGINF (-1e30f)

// scratch (device globals -- no allocation allowed); all layouts LINEAR
__device__ float g_q [BH_*T_*D_];
__device__ float g_k [BH_*T_*D_];
__device__ float g_v [BH_*T_*D_];
__device__ float g_ao[B_*T_*H_*D_];
// pre-rounded tf32 operands
__device__ float g_x [B_*T_*D_];
__device__ float g_wq[D_*H_*D_];
__device__ float g_wk[D_*H_*D_];
__device__ float g_wv[D_*H_*D_];
__device__ float g_wu[H_*D_*D_];

__device__ __forceinline__ unsigned f2tf(float f){
    unsigned u; asm("cvt.rna.tf32.f32 %0, %1;" : "=r"(u) : "f"(f)); return u;
}
__device__ __forceinline__ float f2tff(float f){
    return __uint_as_float(f2tf(f));
}
__device__ __forceinline__ uint4 f2tf4(float4 v){
    return make_uint4(f2tf(v.x), f2tf(v.y), f2tf(v.z), f2tf(v.w));
}
__device__ __forceinline__ uint4 f4bits(float4 v){
    return make_uint4(__float_as_uint(v.x), __float_as_uint(v.y),
                      __float_as_uint(v.z), __float_as_uint(v.w));
}
__device__ __forceinline__ uint32_t saddr(const void* p){
    return (uint32_t)__cvta_generic_to_shared(p);
}
__device__ __forceinline__ void cpa16(uint32_t dst, const void* src){
    asm volatile("cp.async.cg.shared.global [%0], [%1], 16;" :: "r"(dst), "l"(src));
}
#define CP_COMMIT  asm volatile("cp.async.commit_group;")
#define CP_WAIT0   asm volatile("cp.async.wait_group 0;")
#define CP_WAIT1   asm volatile("cp.async.wait_group 1;")

__device__ __forceinline__ void mma8(float4& d,
    unsigned a0, unsigned a1, unsigned a2, unsigned a3,
    unsigned b0, unsigned b1)
{
    asm volatile(
        "mma.sync.aligned.m16n8k8.row.col.f32.tf32.tf32.f32 "
        "{%0,%1,%2,%3},{%4,%5,%6,%7},{%8,%9},{%0,%1,%2,%3};"
        : "+f"(d.x), "+f"(d.y), "+f"(d.z), "+f"(d.w)
        : "r"(a0), "r"(a1), "r"(a2), "r"(a3), "r"(b0), "r"(b1));
}

// ---------------------------------------------------------------------------
// Kernel 0: pre-round inputs to tf32 (Wv gets 128^-0.25 baked in).
// ---------------------------------------------------------------------------
__global__ __launch_bounds__(256, 4)
void prep_kernel(const float* __restrict__ x,  const float* __restrict__ wq,
                 const float* __restrict__ wk, const float* __restrict__ wv,
                 const float* __restrict__ wu)
{
    const int seg = blockIdx.y;
    const float* src; float* dst; int n4; float s = 1.0f;
    if      (seg == 0) { src = x;  dst = g_x;  n4 = (B_*T_*D_)/4; }
    else if (seg == 1) { src = wq; dst = g_wq; n4 = (D_*H_*D_)/4; }
    else if (seg == 2) { src = wk; dst = g_wk; n4 = (D_*H_*D_)/4; }
    else if (seg == 3) { src = wv; dst = g_wv; n4 = (D_*H_*D_)/4; s = 0.29730177875068026f; }
    else               { src = wu; dst = g_wu; n4 = (H_*D_*D_)/4; }

    for (int i = blockIdx.x * blockDim.x + threadIdx.x; i < n4;
         i += gridDim.x * blockDim.x) {
        float4 v = ((const float4*)src)[i];
        v.x *= s; v.y *= s; v.z *= s; v.w *= s;
        ((uint4*)dst)[i] = f2tf4(v);
    }
}

// ---------------------------------------------------------------------------
// Kernel 1: fused QKV projection, tf32 MMA, cp.async, 2 CTAs/SM.  (round-11)
// ---------------------------------------------------------------------------
__global__ __launch_bounds__(256, 2)
void qkv_kernel()
{
    extern __shared__ unsigned smu[];
    unsigned* Xs = smu;             // [128][132]
    unsigned* Ws = smu + 128*132;   // [128][72]

    const int bx = blockIdx.x;     // 64-col tile (0..15)
    const int by = blockIdx.y;     // 128-row tile
    const int mat = blockIdx.z;
    const float* Wg = (mat == 0) ? g_wq : (mat == 1 ? g_wk : g_wv);
    float* outp     = (mat == 0) ? g_q  : (mat == 1 ? g_k  : g_v);

    const int tid = threadIdx.x;
    const int wid = tid >> 5, lane = tid & 31;
    const int g = lane >> 2, c = lane & 3;
    const int wm2 = wid >> 1, wn2 = wid & 1;

    #pragma unroll
    for (int it = 0; it < 16; ++it) {
        int lin = it * 256 + tid;
        int m = lin >> 5, c4 = lin & 31;
        cpa16(saddr(Xs + m*132 + c4*4), g_x + (size_t)(by*128 + m)*128 + c4*4);
    }
    #pragma unroll
    for (int it = 0; it < 8; ++it) {
        int lin = it * 256 + tid;
        int k = lin >> 4, n4 = lin & 15;
        cpa16(saddr(Ws + k*72 + n4*4), Wg + (size_t)k*1024 + bx*64 + n4*4);
    }
    CP_COMMIT;
    CP_WAIT0;
    __syncthreads();

    float4 acc[2][4];
    #pragma unroll
    for (int i = 0; i < 2; ++i)
        #pragma unroll
        for (int j = 0; j < 4; ++j) acc[i][j] = make_float4(0.f, 0.f, 0.f, 0.f);

    #pragma unroll
    for (int k8 = 0; k8 < 16; ++k8) {
        int kk = k8 * 8;
        unsigned a[2][4];
        #pragma unroll
        for (int mt = 0; mt < 2; ++mt) {
            int r = wm2*32 + mt*16 + g;
            a[mt][0] = Xs[r*132 + kk + c];
            a[mt][1] = Xs[(r+8)*132 + kk + c];
            a[mt][2] = Xs[r*132 + kk + c + 4];
            a[mt][3] = Xs[(r+8)*132 + kk + c + 4];
        }
        #pragma unroll
        for (int nt = 0; nt < 4; ++nt) {
            unsigned b0 = Ws[(kk+c  )*72 + wn2*32 + nt*8 + g];
            unsigned b1 = Ws[(kk+c+4)*72 + wn2*32 + nt*8 + g];
            mma8(acc[0][nt], a[0][0], a[0][1], a[0][2], a[0][3], b0, b1);
            mma8(acc[1][nt], a[1][0], a[1][1], a[1][2], a[1][3], b0, b1);
        }
    }

    const int hh = bx >> 1;
    #pragma unroll
    for (int mt = 0; mt < 2; ++mt) {
        int mg0 = by*128 + wm2*32 + mt*16 + g;
        int b0i = mg0 >> 11, t0 = mg0 & (T_ - 1);
        int mg1 = mg0 + 8;
        int b1i = mg1 >> 11, t1 = mg1 & (T_ - 1);
        #pragma unroll
        for (int nt = 0; nt < 4; ++nt) {
            int d = ((bx & 1)*64 + wn2*32 + nt*8 + 2*c);
            float* p0 = outp + ((size_t)(b0i*H_ + hh)*T_ + t0)*D_ + d;
            *(float2*)p0 = make_float2(f2tff(acc[mt][nt].x), f2tff(acc[mt][nt].y));
            float* p1 = outp + ((size_t)(b1i*H_ + hh)*T_ + t1)*D_ + d;
            *(float2*)p1 = make_float2(f2tff(acc[mt][nt].z), f2tff(acc[mt][nt].w));
        }
    }
}

// ---------------------------------------------------------------------------
// Kernel 2: causal flash attention, ROW-OWNERSHIP, tf32 MMA, cp.async db K/V.
// grid (16 q-tiles, 32 bh), 256 threads.  BM=128 queries, BN=64 keys/step.
// Each warp owns 16 query rows for S, softmax, P, PV, and O: zero cross-warp
// data flow inside a step.  Q fragments live in registers (loaded once).
// K and V double-buffered via cp.async: 2 barriers/step, no compute convoys.
// ---------------------------------------------------------------------------
__global__ __launch_bounds__(256, 1)
void attn_kernel()
{
    extern __shared__ unsigned smu[];
    unsigned* Ks = smu;              // [2][64][132]
    unsigned* Vs = Ks + 2*64*132;    // [2][64][136]
    unsigned* Ps = Vs + 2*64*136;    // [128][68]  (warp-local rows)

    const int bh    = blockIdx.y;
    const int qi    = (int)gridDim.x - 1 - (int)blockIdx.x;  // big tiles first
    const int qbase = qi * 128;
    const int tid   = threadIdx.x;
    const int wid   = tid >> 5, lane = tid & 31;
    const int g = lane >> 2, c = lane & 3;
    const int wb = wid * 16;          // this warp's query-row base

    const float* qg = g_q + ((size_t)bh * T_ + qbase) * D_;
    const float* kg = g_k + (size_t)bh * T_ * D_;
    const float* vg = g_v + (size_t)bh * T_ * D_;

    const int   ntiles = 2 * qi + 2;     // always >= 2
    const float sscale = 0.088388347648318447f;   // 128^-0.5

    // prologue: stage K0+V0 (group 0) and K1+V1 (group 1)
    #pragma unroll
    for (int it = 0; it < 8; ++it) {
        int lin = it * 256 + tid;
        int m = lin >> 5, ch = lin & 31;
        cpa16(saddr(Ks + m*132 + ch*4), kg + m*128 + ch*4);
        cpa16(saddr(Vs + m*136 + ch*4), vg + m*128 + ch*4);
    }
    CP_COMMIT;
    #pragma unroll
    for (int it = 0; it < 8; ++it) {
        int lin = it * 256 + tid;
        int m = lin >> 5, ch = lin & 31;
        cpa16(saddr(Ks + 64*132 + m*132 + ch*4), kg + (64 + m)*128 + ch*4);
        cpa16(saddr(Vs + 64*136 + m*136 + ch*4), vg + (64 + m)*128 + ch*4);
    }
    CP_COMMIT;

    // Q fragments to registers (one-time LDG; overlapped with cp.async)
    unsigned qf[16][4];
    #pragma unroll
    for (int k8 = 0; k8 < 16; ++k8) {
        int kk = k8 * 8;
        qf[k8][0] = __float_as_uint(qg[(wb + g    )*128 + kk + c    ]);
        qf[k8][1] = __float_as_uint(qg[(wb + g + 8)*128 + kk + c    ]);
        qf[k8][2] = __float_as_uint(qg[(wb + g    )*128 + kk + c + 4]);
        qf[k8][3] = __float_as_uint(qg[(wb + g + 8)*128 + kk + c + 4]);
    }

    float m0 = NEGINF, m1 = NEGINF, l0 = 0.f, l1 = 0.f;
    float4 oacc[16];
    #pragma unroll
    for (int j = 0; j < 16; ++j) oacc[j] = make_float4(0.f, 0.f, 0.f, 0.f);

    for (int n = 0; n < ntiles; ++n) {
        // K_n,V_n arrived (group n); group n+1 may still be in flight
        if (n + 1 <= ntiles - 1) { CP_WAIT1; } else { CP_WAIT0; }
        __syncthreads();   // bar1: block-wide visibility of bufs[n&1]
                           //       (also WAR: prior step's Ps reads done)

        const unsigned* Kb = Ks + (n & 1)*64*132;
        const unsigned* Vb = Vs + (n & 1)*64*136;

        // S = Q K^T : this warp's 16 rows x all 64 keys
        float4 sacc[8];
        #pragma unroll
        for (int nt = 0; nt < 8; ++nt) sacc[nt] = make_float4(0.f, 0.f, 0.f, 0.f);

        #pragma unroll
        for (int k8 = 0; k8 < 16; ++k8) {
            int kk = k8 * 8;
            #pragma unroll
            for (int nt = 0; nt < 8; ++nt) {
                unsigned b0 = Kb[(nt*8+g)*132 + kk + c];
                unsigned b1 = Kb[(nt*8+g)*132 + kk + c + 4];
                mma8(sacc[nt], qf[k8][0], qf[k8][1], qf[k8][2], qf[k8][3], b0, b1);
            }
        }

        // scale + causal mask (only last two tiles touch the diagonal)
        #pragma unroll
        for (int nt = 0; nt < 8; ++nt) {
            sacc[nt].x *= sscale; sacc[nt].y *= sscale;
            sacc[nt].z *= sscale; sacc[nt].w *= sscale;
        }
        if (n >= 2 * qi) {
            int rg0 = qbase + wb + g, rg1 = rg0 + 8;
            #pragma unroll
            for (int nt = 0; nt < 8; ++nt) {
                int c0 = n*64 + nt*8 + 2*c;
                if (c0     > rg0) sacc[nt].x = NEGINF;
                if (c0 + 1 > rg0) sacc[nt].y = NEGINF;
                if (c0     > rg1) sacc[nt].z = NEGINF;
                if (c0 + 1 > rg1) sacc[nt].w = NEGINF;
            }
        }

        // online softmax, rows r0 = wb+g, r1 = r0+8 (4-lane group reduce)
        float mx0 = NEGINF, mx1 = NEGINF;
        #pragma unroll
        for (int nt = 0; nt < 8; ++nt) {
            mx0 = fmaxf(mx0, fmaxf(sacc[nt].x, sacc[nt].y));
            mx1 = fmaxf(mx1, fmaxf(sacc[nt].z, sacc[nt].w));
        }
        mx0 = fmaxf(mx0, __shfl_xor_sync(0xffffffffu, mx0, 1));
        mx0 = fmaxf(mx0, __shfl_xor_sync(0xffffffffu, mx0, 2));
        mx1 = fmaxf(mx1, __shfl_xor_sync(0xffffffffu, mx1, 1));
        mx1 = fmaxf(mx1, __shfl_xor_sync(0xffffffffu, mx1, 2));

        float mn0 = fmaxf(m0, mx0), mn1 = fmaxf(m1, mx1);
        float al0 = __expf(m0 - mn0), al1 = __expf(m1 - mn1);
        m0 = mn0; m1 = mn1;

        int r0 = wb + g, r1 = r0 + 8;
        float rs0 = 0.f, rs1 = 0.f;
        #pragma unroll
        for (int nt = 0; nt < 8; ++nt) {
            float px = __expf(sacc[nt].x - mn0);
            float py = __expf(sacc[nt].y - mn0);
            float pz = __expf(sacc[nt].z - mn1);
            float pw = __expf(sacc[nt].w - mn1);
            rs0 += px + py; rs1 += pz + pw;
            *(uint2*)&Ps[r0*68 + nt*8 + 2*c] = make_uint2(f2tf(px), f2tf(py));
            *(uint2*)&Ps[r1*68 + nt*8 + 2*c] = make_uint2(f2tf(pz), f2tf(pw));
        }
        rs0 += __shfl_xor_sync(0xffffffffu, rs0, 1);
        rs0 += __shfl_xor_sync(0xffffffffu, rs0, 2);
        rs1 += __shfl_xor_sync(0xffffffffu, rs1, 1);
        rs1 += __shfl_xor_sync(0xffffffffu, rs1, 2);
        l0 = l0 * al0 + rs0;
        l1 = l1 * al1 + rs1;

        __syncwarp();   // Ps RAW: softmax STS -> PV LDS (warp-local rows)

        // rescale O (same rows: alpha straight from registers)
        #pragma unroll
        for (int nt = 0; nt < 16; ++nt) {
            oacc[nt].x *= al0; oacc[nt].y *= al0;
            oacc[nt].z *= al1; oacc[nt].w *= al1;
        }

        // O += P @ V : this warp's 16 rows x all 128 d-cols
        #pragma unroll
        for (int k8 = 0; k8 < 8; ++k8) {
            int kk = k8 * 8;
            unsigned a0 = Ps[r0*68 + kk + c];
            unsigned a1 = Ps[r1*68 + kk + c];
            unsigned a2 = Ps[r0*68 + kk + c + 4];
            unsigned a3 = Ps[r1*68 + kk + c + 4];
            #pragma unroll
            for (int nt = 0; nt < 16; ++nt) {
                unsigned b0 = Vb[(kk+c  )*136 + nt*8 + g];
                unsigned b1 = Vb[(kk+c+4)*136 + nt*8 + g];
                mma8(oacc[nt], a0, a1, a2, a3, b0, b1);
            }
        }

        __syncthreads();   // bar2: all warps done reading bufs[n&1]

        // stage K_{n+2}+V_{n+2} into the buffer just freed
        if (n + 2 <= ntiles - 1) {
            const float* kt = kg + (size_t)(n+2) * 64 * D_;
            const float* vt = vg + (size_t)(n+2) * 64 * D_;
            unsigned* Kd = Ks + (n & 1)*64*132;
            unsigned* Vd = Vs + (n & 1)*64*136;
            #pragma unroll
            for (int it = 0; it < 8; ++it) {
                int lin = it * 256 + tid;
                int m = lin >> 5, ch = lin & 31;
                cpa16(saddr(Kd + m*132 + ch*4), kt + m*128 + ch*4);
                cpa16(saddr(Vd + m*136 + ch*4), vt + m*128 + ch*4);
            }
            CP_COMMIT;
        }
    }

    // epilogue: everything warp-local
    float inv0 = 1.f / l0, inv1 = 1.f / l1;
    const int bb = bh >> 3, hh = bh & 7;
    int t0 = qbase + wb + g;
    #pragma unroll
    for (int nt = 0; nt < 16; ++nt) {
        int d = nt*8 + 2*c;
        float* p0 = g_ao + ((size_t)(bb*T_ + t0))*(H_*D_) + hh*128 + d;
        *(float2*)p0 = make_float2(f2tff(oacc[nt].x * inv0),
                                   f2tff(oacc[nt].y * inv0));
        float* p1 = g_ao + ((size_t)(bb*T_ + t0 + 8))*(H_*D_) + hh*128 + d;
        *(float2*)p1 = make_float2(f2tff(oacc[nt].z * inv1),
                                   f2tff(oacc[nt].w * inv1));
    }
}

// ---------------------------------------------------------------------------
// Kernel 3: output projection, tf32 MMA, register double-buffered k-chunks.
// ---------------------------------------------------------------------------
__global__ __launch_bounds__(256, 1)
void proj_kernel(const float* __restrict__ bu, float* __restrict__ out)
{
    extern __shared__ unsigned smu[];
    unsigned* As = smu;           // [64][68]
    unsigned* Bs = smu + 64*68;   // [64][136]

    const int by  = blockIdx.x;
    const int tid = threadIdx.x;
    const int wid = tid >> 5, lane = tid & 31;
    const int g = lane >> 2, c = lane & 3;
    const int wm = wid >> 1, wn = wid & 1;

    float4 acc[8];
    #pragma unroll
    for (int j = 0; j < 8; ++j) acc[j] = make_float4(0.f, 0.f, 0.f, 0.f);

    float4 areg[4], breg[8];
    #pragma unroll
    for (int it = 0; it < 4; ++it) {
        int lin = it * 256 + tid;
        int m = lin >> 4, c4 = lin & 15;
        areg[it] = *(const float4*)(g_ao + (size_t)(by*64 + m)*1024 + c4*4);
    }
    #pragma unroll
    for (int it = 0; it < 8; ++it) {
        int lin = it * 256 + tid;
        int k = lin >> 5, n4 = lin & 31;
        breg[it] = *(const float4*)(g_wu + (size_t)k*128 + n4*4);
    }

    for (int kc = 0; kc < 16; ++kc) {
        __syncthreads();
        #pragma unroll
        for (int it = 0; it < 4; ++it) {
            int lin = it * 256 + tid;
            int m = lin >> 4, c4 = lin & 15;
            *(uint4*)(As + m*68 + c4*4) = f4bits(areg[it]);
        }
        #pragma unroll
        for (int it = 0; it < 8; ++it) {
            int lin = it * 256 + tid;
            int k = lin >> 5, n4 = lin & 31;
            *(uint4*)(Bs + k*136 + n4*4) = f4bits(breg[it]);
        }
        __syncthreads();

        if (kc < 15) {
            #pragma unroll
            for (int it = 0; it < 4; ++it) {
                int lin = it * 256 + tid;
                int m = lin >> 4, c4 = lin & 15;
                areg[it] = *(const float4*)(g_ao + (size_t)(by*64 + m)*1024
                                                 + (kc+1)*64 + c4*4);
            }
            #pragma unroll
            for (int it = 0; it < 8; ++it) {
                int lin = it * 256 + tid;
                int k = lin >> 5, n4 = lin & 31;
                breg[it] = *(const float4*)(g_wu + (size_t)((kc+1)*64 + k)*128 + n4*4);
            }
        }

        #pragma unroll
        for (int k8 = 0; k8 < 8; ++k8) {
            int kk = k8 * 8;
            int r = wm*16 + g;
            unsigned a0 = As[r*68 + kk + c];
            unsigned a1 = As[(r+8)*68 + kk + c];
            unsigned a2 = As[r*68 + kk + c + 4];
            unsigned a3 = As[(r+8)*68 + kk + c + 4];
            #pragma unroll
            for (int nt = 0; nt < 8; ++nt) {
                unsigned b0 = Bs[(kk+c  )*136 + wn*64 + nt*8 + g];
                unsigned b1 = Bs[(kk+c+4)*136 + wn*64 + nt*8 + g];
                mma8(acc[nt], a0, a1, a2, a3, b0, b1);
            }
        }
    }

    #pragma unroll
    for (int nt = 0; nt < 8; ++nt) {
        int d = wn*64 + nt*8 + 2*c;
        float bv0 = bu[d], bv1 = bu[d + 1];
        int m0 = by*64 + wm*16 + g;
        *(float2*)(out + (size_t)m0*128 + d) =
            make_float2(acc[nt].x + bv0, acc[nt].y + bv1);
        *(float2*)(out + (size_t)(m0 + 8)*128 + d) =
            make_float2(acc[nt].z + bv0, acc[nt].w + bv1);
    }
}

// ---------------------------------------------------------------------------
extern "C" void kernel_launch(void* const* d_in, const int* in_sizes, int n_in,
                              void* d_out, int out_size)
{
    const float* x  = (const float*)d_in[0];
    const float* Wq = (const float*)d_in[1];
    const float* Wk = (const float*)d_in[2];
    const float* Wv = (const float*)d_in[3];
    const float* Wu = (const float*)d_in[4];
    const float* bu = (const float*)d_in[5];
    float* out = (float*)d_out;

    const int SMEM1 = (128*132 + 128*72) * (int)sizeof(unsigned);            // 104448
    const int SMEM2 = (2*64*132 + 2*64*136 + 128*68) * (int)sizeof(unsigned); // 172032
    const int SMEM3 = (64*68 + 64*136) * (int)sizeof(unsigned);              // 52224

    cudaFuncSetAttribute(qkv_kernel,  cudaFuncAttributeMaxDynamicSharedMemorySize, SMEM1);
    cudaFuncSetAttribute(attn_kernel, cudaFuncAttributeMaxDynamicSharedMemorySize, SMEM2);
    cudaFuncSetAttribute(proj_kernel, cudaFuncAttributeMaxDynamicSharedMemorySize, SMEM3);

    prep_kernel<<<dim3(128, 5), 256>>>(x, Wq, Wk, Wv, Wu);
    qkv_kernel<<<dim3(16, 64, 3), 256, SMEM1>>>();
    attn_kernel<<<dim3(16, 32), 256, SMEM2>>>();
    proj_kernel<<<dim3(128), 256, SMEM3>>>(bu, out);
}

// round 17
// speedup vs baseline: 2.2671x; 1.1604x over previous
#include <cuda_runtime.h>
#include <cuda_bf16.h>
#include <math.h>
#include <stdint.h>

#define B_  4
#define T_  2048
#define D_  128
#define H_  8
#define BH_ (B_*H_)
#define NEGINF (-1e30f)

// scratch (device globals -- no allocation allowed); all layouts LINEAR
// g_q/g_k hold bf16 data (viewed as bf16x2 words): [bh][t][d/2 words]
__device__ float g_q [BH_*T_*D_];   // used as bf16 backing store
__device__ float g_k [BH_*T_*D_];   // used as bf16 backing store
__device__ float g_v [BH_*T_*D_];
__device__ float g_ao[B_*T_*H_*D_];
// pre-rounded tf32 operands
__device__ float g_x [B_*T_*D_];
__device__ float g_wq[D_*H_*D_];
__device__ float g_wk[D_*H_*D_];
__device__ float g_wv[D_*H_*D_];
__device__ float g_wu[H_*D_*D_];

__device__ __forceinline__ unsigned f2tf(float f){
    unsigned u; asm("cvt.rna.tf32.f32 %0, %1;" : "=r"(u) : "f"(f)); return u;
}
__device__ __forceinline__ float f2tff(float f){
    return __uint_as_float(f2tf(f));
}
__device__ __forceinline__ uint4 f2tf4(float4 v){
    return make_uint4(f2tf(v.x), f2tf(v.y), f2tf(v.z), f2tf(v.w));
}
__device__ __forceinline__ uint4 f4bits(float4 v){
    return make_uint4(__float_as_uint(v.x), __float_as_uint(v.y),
                      __float_as_uint(v.z), __float_as_uint(v.w));
}
// pack two fp32 into bf16x2 word: lo -> low half, hi -> high half
__device__ __forceinline__ unsigned pk_bf16(float lo, float hi){
    unsigned r;
    asm("cvt.rn.bf16x2.f32 %0, %1, %2;" : "=r"(r) : "f"(hi), "f"(lo));
    return r;
}
__device__ __forceinline__ uint32_t saddr(const void* p){
    return (uint32_t)__cvta_generic_to_shared(p);
}
__device__ __forceinline__ void cpa16(uint32_t dst, const void* src){
    asm volatile("cp.async.cg.shared.global [%0], [%1], 16;" :: "r"(dst), "l"(src));
}
#define CP_COMMIT  asm volatile("cp.async.commit_group;")
#define CP_WAIT0   asm volatile("cp.async.wait_group 0;")
#define CP_WAIT1   asm volatile("cp.async.wait_group 1;")

// tf32 m16n8k8
__device__ __forceinline__ void mma8(float4& d,
    unsigned a0, unsigned a1, unsigned a2, unsigned a3,
    unsigned b0, unsigned b1)
{
    asm volatile(
        "mma.sync.aligned.m16n8k8.row.col.f32.tf32.tf32.f32 "
        "{%0,%1,%2,%3},{%4,%5,%6,%7},{%8,%9},{%0,%1,%2,%3};"
        : "+f"(d.x), "+f"(d.y), "+f"(d.z), "+f"(d.w)
        : "r"(a0), "r"(a1), "r"(a2), "r"(a3), "r"(b0), "r"(b1));
}

// bf16 m16n8k16 (2x MACs per instruction vs tf32 k8)
__device__ __forceinline__ void mma16(float4& d,
    unsigned a0, unsigned a1, unsigned a2, unsigned a3,
    unsigned b0, unsigned b1)
{
    asm volatile(
        "mma.sync.aligned.m16n8k16.row.col.f32.bf16.bf16.f32 "
        "{%0,%1,%2,%3},{%4,%5,%6,%7},{%8,%9},{%0,%1,%2,%3};"
        : "+f"(d.x), "+f"(d.y), "+f"(d.z), "+f"(d.w)
        : "r"(a0), "r"(a1), "r"(a2), "r"(a3), "r"(b0), "r"(b1));
}

// ---------------------------------------------------------------------------
// Kernel 0: pre-round inputs to tf32 (Wv gets 128^-0.25 baked in).
// ---------------------------------------------------------------------------
__global__ __launch_bounds__(256, 4)
void prep_kernel(const float* __restrict__ x,  const float* __restrict__ wq,
                 const float* __restrict__ wk, const float* __restrict__ wv,
                 const float* __restrict__ wu)
{
    const int seg = blockIdx.y;
    const float* src; float* dst; int n4; float s = 1.0f;
    if      (seg == 0) { src = x;  dst = g_x;  n4 = (B_*T_*D_)/4; }
    else if (seg == 1) { src = wq; dst = g_wq; n4 = (D_*H_*D_)/4; }
    else if (seg == 2) { src = wk; dst = g_wk; n4 = (D_*H_*D_)/4; }
    else if (seg == 3) { src = wv; dst = g_wv; n4 = (D_*H_*D_)/4; s = 0.29730177875068026f; }
    else               { src = wu; dst = g_wu; n4 = (H_*D_*D_)/4; }

    for (int i = blockIdx.x * blockDim.x + threadIdx.x; i < n4;
         i += gridDim.x * blockDim.x) {
        float4 v = ((const float4*)src)[i];
        v.x *= s; v.y *= s; v.z *= s; v.w *= s;
        ((uint4*)dst)[i] = f2tf4(v);
    }
}

// ---------------------------------------------------------------------------
// Kernel 1: fused QKV projection, tf32 MMA, cp.async, 2 CTAs/SM.
// q/k outputs rounded to bf16 (bf16x2 words over d);  v stays tf32 fp32.
// ---------------------------------------------------------------------------
__global__ __launch_bounds__(256, 2)
void qkv_kernel()
{
    extern __shared__ unsigned smu[];
    unsigned* Xs = smu;             // [128][132]
    unsigned* Ws = smu + 128*132;   // [128][72]

    const int bx = blockIdx.x;     // 64-col tile (0..15)
    const int by = blockIdx.y;     // 128-row tile
    const int mat = blockIdx.z;
    const float* Wg = (mat == 0) ? g_wq : (mat == 1 ? g_wk : g_wv);
    float* outp     = (mat == 0) ? g_q  : (mat == 1 ? g_k  : g_v);

    const int tid = threadIdx.x;
    const int wid = tid >> 5, lane = tid & 31;
    const int g = lane >> 2, c = lane & 3;
    const int wm2 = wid >> 1, wn2 = wid & 1;

    #pragma unroll
    for (int it = 0; it < 16; ++it) {
        int lin = it * 256 + tid;
        int m = lin >> 5, c4 = lin & 31;
        cpa16(saddr(Xs + m*132 + c4*4), g_x + (size_t)(by*128 + m)*128 + c4*4);
    }
    #pragma unroll
    for (int it = 0; it < 8; ++it) {
        int lin = it * 256 + tid;
        int k = lin >> 4, n4 = lin & 15;
        cpa16(saddr(Ws + k*72 + n4*4), Wg + (size_t)k*1024 + bx*64 + n4*4);
    }
    CP_COMMIT;
    CP_WAIT0;
    __syncthreads();

    float4 acc[2][4];
    #pragma unroll
    for (int i = 0; i < 2; ++i)
        #pragma unroll
        for (int j = 0; j < 4; ++j) acc[i][j] = make_float4(0.f, 0.f, 0.f, 0.f);

    #pragma unroll
    for (int k8 = 0; k8 < 16; ++k8) {
        int kk = k8 * 8;
        unsigned a[2][4];
        #pragma unroll
        for (int mt = 0; mt < 2; ++mt) {
            int r = wm2*32 + mt*16 + g;
            a[mt][0] = Xs[r*132 + kk + c];
            a[mt][1] = Xs[(r+8)*132 + kk + c];
            a[mt][2] = Xs[r*132 + kk + c + 4];
            a[mt][3] = Xs[(r+8)*132 + kk + c + 4];
        }
        #pragma unroll
        for (int nt = 0; nt < 4; ++nt) {
            unsigned b0 = Ws[(kk+c  )*72 + wn2*32 + nt*8 + g];
            unsigned b1 = Ws[(kk+c+4)*72 + wn2*32 + nt*8 + g];
            mma8(acc[0][nt], a[0][0], a[0][1], a[0][2], a[0][3], b0, b1);
            mma8(acc[1][nt], a[1][0], a[1][1], a[1][2], a[1][3], b0, b1);
        }
    }

    const int hh = bx >> 1;
    #pragma unroll
    for (int mt = 0; mt < 2; ++mt) {
        int mg0 = by*128 + wm2*32 + mt*16 + g;
        int b0i = mg0 >> 11, t0 = mg0 & (T_ - 1);
        int mg1 = mg0 + 8;
        int b1i = mg1 >> 11, t1 = mg1 & (T_ - 1);
        #pragma unroll
        for (int nt = 0; nt < 4; ++nt) {
            int d = ((bx & 1)*64 + wn2*32 + nt*8 + 2*c);
            if (mat < 2) {
                // bf16x2 word per (d, d+1) pair;  word index = d/2 of 64/row
                unsigned* o32 = (unsigned*)outp;
                o32[((size_t)(b0i*H_ + hh)*T_ + t0)*64 + (d >> 1)] =
                    pk_bf16(acc[mt][nt].x, acc[mt][nt].y);
                o32[((size_t)(b1i*H_ + hh)*T_ + t1)*64 + (d >> 1)] =
                    pk_bf16(acc[mt][nt].z, acc[mt][nt].w);
            } else {
                float* p0 = outp + ((size_t)(b0i*H_ + hh)*T_ + t0)*D_ + d;
                *(float2*)p0 = make_float2(f2tff(acc[mt][nt].x), f2tff(acc[mt][nt].y));
                float* p1 = outp + ((size_t)(b1i*H_ + hh)*T_ + t1)*D_ + d;
                *(float2*)p1 = make_float2(f2tff(acc[mt][nt].z), f2tff(acc[mt][nt].w));
            }
        }
    }
}

// ---------------------------------------------------------------------------
// Kernel 2: causal flash attention, ROW-OWNERSHIP.
// S-GEMM: bf16 m16n8k16 (half the HMMA count, half the K smem+LDS traffic).
// PV:     tf32 m16n8k8 (unchanged).
// grid (16 q-tiles, 32 bh), 256 threads.  BM=128, BN=64, db K/V cp.async.
// Ks: bf16x2 words [2][64][68]  (word-col = k/2, 64 cols + pad 4)
// ---------------------------------------------------------------------------
__global__ __launch_bounds__(256, 1)
void attn_kernel()
{
    extern __shared__ unsigned smu[];
    unsigned* Ks = smu;              // [2][64][68]  bf16x2 words
    unsigned* Vs = Ks + 2*64*68;     // [2][64][136] tf32
    unsigned* Ps = Vs + 2*64*136;    // [128][68]    tf32 (warp-local rows)

    const int bh    = blockIdx.y;
    const int qi    = (int)gridDim.x - 1 - (int)blockIdx.x;  // big tiles first
    const int qbase = qi * 128;
    const int tid   = threadIdx.x;
    const int wid   = tid >> 5, lane = tid & 31;
    const int g = lane >> 2, c = lane & 3;
    const int wb = wid * 16;          // this warp's query-row base

    const unsigned* Qw = (const unsigned*)g_q + ((size_t)bh * T_ + qbase) * 64;
    const char*     kgb = (const char*)g_k + (size_t)bh * T_ * 256;  // 256B/row
    const float*    vg  = g_v + (size_t)bh * T_ * D_;

    const int   ntiles = 2 * qi + 2;     // always >= 2
    const float sscale = 0.088388347648318447f;   // 128^-0.5

    // prologue: stage K0+V0 (group 0) and K1+V1 (group 1)
    // K row = 256 bytes = 16 chunks;  V row = 512 bytes = 32 chunks
    #pragma unroll
    for (int it = 0; it < 4; ++it) {          // K0: 64 rows x 16 chunks
        int lin = it * 256 + tid;
        int m = lin >> 4, ch = lin & 15;
        cpa16(saddr(Ks + m*68 + ch*4), kgb + m*256 + ch*16);
    }
    #pragma unroll
    for (int it = 0; it < 8; ++it) {          // V0
        int lin = it * 256 + tid;
        int m = lin >> 5, ch = lin & 31;
        cpa16(saddr(Vs + m*136 + ch*4), vg + m*128 + ch*4);
    }
    CP_COMMIT;
    #pragma unroll
    for (int it = 0; it < 4; ++it) {          // K1
        int lin = it * 256 + tid;
        int m = lin >> 4, ch = lin & 15;
        cpa16(saddr(Ks + 64*68 + m*68 + ch*4), kgb + (64 + m)*256 + ch*16);
    }
    #pragma unroll
    for (int it = 0; it < 8; ++it) {          // V1
        int lin = it * 256 + tid;
        int m = lin >> 5, ch = lin & 31;
        cpa16(saddr(Vs + 64*136 + m*136 + ch*4), vg + (64 + m)*128 + ch*4);
    }
    CP_COMMIT;

    // Q fragments to registers (bf16x2 words; one-time LDG)
    unsigned qf[8][4];
    #pragma unroll
    for (int k16 = 0; k16 < 8; ++k16) {
        qf[k16][0] = Qw[(wb + g    )*64 + k16*8 + c    ];
        qf[k16][1] = Qw[(wb + g + 8)*64 + k16*8 + c    ];
        qf[k16][2] = Qw[(wb + g    )*64 + k16*8 + c + 4];
        qf[k16][3] = Qw[(wb + g + 8)*64 + k16*8 + c + 4];
    }

    float m0 = NEGINF, m1 = NEGINF, l0 = 0.f, l1 = 0.f;
    float4 oacc[16];
    #pragma unroll
    for (int j = 0; j < 16; ++j) oacc[j] = make_float4(0.f, 0.f, 0.f, 0.f);

    for (int n = 0; n < ntiles; ++n) {
        if (n + 1 <= ntiles - 1) { CP_WAIT1; } else { CP_WAIT0; }
        __syncthreads();   // bar1: visibility of bufs[n&1]; prior Ps reads done

        const unsigned* Kb = Ks + (n & 1)*64*68;
        const unsigned* Vb = Vs + (n & 1)*64*136;

        // S = Q K^T : bf16 m16n8k16, 8 k-steps x 8 key-tiles = 64 HMMA
        float4 sacc[8];
        #pragma unroll
        for (int nt = 0; nt < 8; ++nt) sacc[nt] = make_float4(0.f, 0.f, 0.f, 0.f);

        #pragma unroll
        for (int k16 = 0; k16 < 8; ++k16) {
            #pragma unroll
            for (int nt = 0; nt < 8; ++nt) {
                unsigned b0 = Kb[(nt*8+g)*68 + k16*8 + c];
                unsigned b1 = Kb[(nt*8+g)*68 + k16*8 + c + 4];
                mma16(sacc[nt], qf[k16][0], qf[k16][1], qf[k16][2], qf[k16][3],
                      b0, b1);
            }
        }

        // scale + causal mask (only last two tiles touch the diagonal)
        #pragma unroll
        for (int nt = 0; nt < 8; ++nt) {
            sacc[nt].x *= sscale; sacc[nt].y *= sscale;
            sacc[nt].z *= sscale; sacc[nt].w *= sscale;
        }
        if (n >= 2 * qi) {
            int rg0 = qbase + wb + g, rg1 = rg0 + 8;
            #pragma unroll
            for (int nt = 0; nt < 8; ++nt) {
                int c0 = n*64 + nt*8 + 2*c;
                if (c0     > rg0) sacc[nt].x = NEGINF;
                if (c0 + 1 > rg0) sacc[nt].y = NEGINF;
                if (c0     > rg1) sacc[nt].z = NEGINF;
                if (c0 + 1 > rg1) sacc[nt].w = NEGINF;
            }
        }

        // online softmax, rows r0 = wb+g, r1 = r0+8 (4-lane group reduce)
        float mx0 = NEGINF, mx1 = NEGINF;
        #pragma unroll
        for (int nt = 0; nt < 8; ++nt) {
            mx0 = fmaxf(mx0, fmaxf(sacc[nt].x, sacc[nt].y));
            mx1 = fmaxf(mx1, fmaxf(sacc[nt].z, sacc[nt].w));
        }
        mx0 = fmaxf(mx0, __shfl_xor_sync(0xffffffffu, mx0, 1));
        mx0 = fmaxf(mx0, __shfl_xor_sync(0xffffffffu, mx0, 2));
        mx1 = fmaxf(mx1, __shfl_xor_sync(0xffffffffu, mx1, 1));
        mx1 = fmaxf(mx1, __shfl_xor_sync(0xffffffffu, mx1, 2));

        float mn0 = fmaxf(m0, mx0), mn1 = fmaxf(m1, mx1);
        float al0 = __expf(m0 - mn0), al1 = __expf(m1 - mn1);
        m0 = mn0; m1 = mn1;

        int r0 = wb + g, r1 = r0 + 8;
        float rs0 = 0.f, rs1 = 0.f;
        #pragma unroll
        for (int nt = 0; nt < 8; ++nt) {
            float px = __expf(sacc[nt].x - mn0);
            float py = __expf(sacc[nt].y - mn0);
            float pz = __expf(sacc[nt].z - mn1);
            float pw = __expf(sacc[nt].w - mn1);
            rs0 += px + py; rs1 += pz + pw;
            *(uint2*)&Ps[r0*68 + nt*8 + 2*c] = make_uint2(f2tf(px), f2tf(py));
            *(uint2*)&Ps[r1*68 + nt*8 + 2*c] = make_uint2(f2tf(pz), f2tf(pw));
        }
        rs0 += __shfl_xor_sync(0xffffffffu, rs0, 1);
        rs0 += __shfl_xor_sync(0xffffffffu, rs0, 2);
        rs1 += __shfl_xor_sync(0xffffffffu, rs1, 1);
        rs1 += __shfl_xor_sync(0xffffffffu, rs1, 2);
        l0 = l0 * al0 + rs0;
        l1 = l1 * al1 + rs1;

        __syncwarp();   // Ps RAW: softmax STS -> PV LDS (warp-local rows)

        // rescale O (same rows: alpha straight from registers)
        #pragma unroll
        for (int nt = 0; nt < 16; ++nt) {
            oacc[nt].x *= al0; oacc[nt].y *= al0;
            oacc[nt].z *= al1; oacc[nt].w *= al1;
        }

        // O += P @ V : tf32 m16n8k8, this warp's 16 rows x 128 d-cols
        #pragma unroll
        for (int k8 = 0; k8 < 8; ++k8) {
            int kk = k8 * 8;
            unsigned a0 = Ps[r0*68 + kk + c];
            unsigned a1 = Ps[r1*68 + kk + c];
            unsigned a2 = Ps[r0*68 + kk + c + 4];
            unsigned a3 = Ps[r1*68 + kk + c + 4];
            #pragma unroll
            for (int nt = 0; nt < 16; ++nt) {
                unsigned b0 = Vb[(kk+c  )*136 + nt*8 + g];
                unsigned b1 = Vb[(kk+c+4)*136 + nt*8 + g];
                mma8(oacc[nt], a0, a1, a2, a3, b0, b1);
            }
        }

        __syncthreads();   // bar2: all warps done reading bufs[n&1]

        // stage K_{n+2}+V_{n+2} into the buffer just freed
        if (n + 2 <= ntiles - 1) {
            const char*  kt = kgb + (size_t)(n+2) * 64 * 256;
            const float* vt = vg + (size_t)(n+2) * 64 * D_;
            unsigned* Kd = Ks + (n & 1)*64*68;
            unsigned* Vd = Vs + (n & 1)*64*136;
            #pragma unroll
            for (int it = 0; it < 4; ++it) {
                int lin = it * 256 + tid;
                int m = lin >> 4, ch = lin & 15;
                cpa16(saddr(Kd + m*68 + ch*4), kt + m*256 + ch*16);
            }
            #pragma unroll
            for (int it = 0; it < 8; ++it) {
                int lin = it * 256 + tid;
                int m = lin >> 5, ch = lin & 31;
                cpa16(saddr(Vd + m*136 + ch*4), vt + m*128 + ch*4);
            }
            CP_COMMIT;
        }
    }

    // epilogue: everything warp-local
    float inv0 = 1.f / l0, inv1 = 1.f / l1;
    const int bb = bh >> 3, hh = bh & 7;
    int t0 = qbase + wb + g;
    #pragma unroll
    for (int nt = 0; nt < 16; ++nt) {
        int d = nt*8 + 2*c;
        float* p0 = g_ao + ((size_t)(bb*T_ + t0))*(H_*D_) + hh*128 + d;
        *(float2*)p0 = make_float2(f2tff(oacc[nt].x * inv0),
                                   f2tff(oacc[nt].y * inv0));
        float* p1 = g_ao + ((size_t)(bb*T_ + t0 + 8))*(H_*D_) + hh*128 + d;
        *(float2*)p1 = make_float2(f2tff(oacc[nt].z * inv1),
                                   f2tff(oacc[nt].w * inv1));
    }
}

// ---------------------------------------------------------------------------
// Kernel 3: output projection, tf32 MMA, register double-buffered k-chunks.
// ---------------------------------------------------------------------------
__global__ __launch_bounds__(256, 1)
void proj_kernel(const float* __restrict__ bu, float* __restrict__ out)
{
    extern __shared__ unsigned smu[];
    unsigned* As = smu;           // [64][68]
    unsigned* Bs = smu + 64*68;   // [64][136]

    const int by  = blockIdx.x;
    const int tid = threadIdx.x;
    const int wid = tid >> 5, lane = tid & 31;
    const int g = lane >> 2, c = lane & 3;
    const int wm = wid >> 1, wn = wid & 1;

    float4 acc[8];
    #pragma unroll
    for (int j = 0; j < 8; ++j) acc[j] = make_float4(0.f, 0.f, 0.f, 0.f);

    float4 areg[4], breg[8];
    #pragma unroll
    for (int it = 0; it < 4; ++it) {
        int lin = it * 256 + tid;
        int m = lin >> 4, c4 = lin & 15;
        areg[it] = *(const float4*)(g_ao + (size_t)(by*64 + m)*1024 + c4*4);
    }
    #pragma unroll
    for (int it = 0; it < 8; ++it) {
        int lin = it * 256 + tid;
        int k = lin >> 5, n4 = lin & 31;
        breg[it] = *(const float4*)(g_wu + (size_t)k*128 + n4*4);
    }

    for (int kc = 0; kc < 16; ++kc) {
        __syncthreads();
        #pragma unroll
        for (int it = 0; it < 4; ++it) {
            int lin = it * 256 + tid;
            int m = lin >> 4, c4 = lin & 15;
            *(uint4*)(As + m*68 + c4*4) = f4bits(areg[it]);
        }
        #pragma unroll
        for (int it = 0; it < 8; ++it) {
            int lin = it * 256 + tid;
            int k = lin >> 5, n4 = lin & 31;
            *(uint4*)(Bs + k*136 + n4*4) = f4bits(breg[it]);
        }
        __syncthreads();

        if (kc < 15) {
            #pragma unroll
            for (int it = 0; it < 4; ++it) {
                int lin = it * 256 + tid;
                int m = lin >> 4, c4 = lin & 15;
                areg[it] = *(const float4*)(g_ao + (size_t)(by*64 + m)*1024
                                                 + (kc+1)*64 + c4*4);
            }
            #pragma unroll
            for (int it = 0; it < 8; ++it) {
                int lin = it * 256 + tid;
                int k = lin >> 5, n4 = lin & 31;
                breg[it] = *(const float4*)(g_wu + (size_t)((kc+1)*64 + k)*128 + n4*4);
            }
        }

        #pragma unroll
        for (int k8 = 0; k8 < 8; ++k8) {
            int kk = k8 * 8;
            int r = wm*16 + g;
            unsigned a0 = As[r*68 + kk + c];
            unsigned a1 = As[(r+8)*68 + kk + c];
            unsigned a2 = As[r*68 + kk + c + 4];
            unsigned a3 = As[(r+8)*68 + kk + c + 4];
            #pragma unroll
            for (int nt = 0; nt < 8; ++nt) {
                unsigned b0 = Bs[(kk+c  )*136 + wn*64 + nt*8 + g];
                unsigned b1 = Bs[(kk+c+4)*136 + wn*64 + nt*8 + g];
                mma8(acc[nt], a0, a1, a2, a3, b0, b1);
            }
        }
    }

    #pragma unroll
    for (int nt = 0; nt < 8; ++nt) {
        int d = wn*64 + nt*8 + 2*c;
        float bv0 = bu[d], bv1 = bu[d + 1];
        int m0 = by*64 + wm*16 + g;
        *(float2*)(out + (size_t)m0*128 + d) =
            make_float2(acc[nt].x + bv0, acc[nt].y + bv1);
        *(float2*)(out + (size_t)(m0 + 8)*128 + d) =
            make_float2(acc[nt].z + bv0, acc[nt].w + bv1);
    }
}

// ---------------------------------------------------------------------------
extern "C" void kernel_launch(void* const* d_in, const int* in_sizes, int n_in,
                              void* d_out, int out_size)
{
    const float* x  = (const float*)d_in[0];
    const float* Wq = (const float*)d_in[1];
    const float* Wk = (const float*)d_in[2];
    const float* Wv = (const float*)d_in[3];
    const float* Wu = (const float*)d_in[4];
    const float* bu = (const float*)d_in[5];
    float* out = (float*)d_out;

    const int SMEM1 = (128*132 + 128*72) * (int)sizeof(unsigned);            // 104448
    const int SMEM2 = (2*64*68 + 2*64*136 + 128*68) * (int)sizeof(unsigned); // 139264
    const int SMEM3 = (64*68 + 64*136) * (int)sizeof(unsigned);              // 52224

    cudaFuncSetAttribute(qkv_kernel,  cudaFuncAttributeMaxDynamicSharedMemorySize, SMEM1);
    cudaFuncSetAttribute(attn_kernel, cudaFuncAttributeMaxDynamicSharedMemorySize, SMEM2);
    cudaFuncSetAttribute(proj_kernel, cudaFuncAttributeMaxDynamicSharedMemorySize, SMEM3);

    prep_kernel<<<dim3(128, 5), 256>>>(x, Wq, Wk, Wv, Wu);
    qkv_kernel<<<dim3(16, 64, 3), 256, SMEM1>>>();
    attn_kernel<<<dim3(16, 32), 256, SMEM2>>>();
    proj_kernel<<<dim3(128), 256, SMEM3>>>(bu, out);
}